// round 11
// baseline (speedup 1.0000x reference)
#include <cuda_runtime.h>

#define MAXN 100000
#define MAXE 1600000
#define NEG 0.2f

typedef unsigned long long ull;

// ---------------- scratch (static device globals; no allocation) -------------
__device__ float g_h0 [MAXN * 16];    // relu(x@W0)
__device__ float g_hl [MAXN * 96];    // source transform (current layer)
__device__ float g_hr [MAXN * 96];    // target transform (current layer)
__device__ float g_acc[MAXN * 96];    // layer-1 accumulator = skip + b1 + msgs
__device__ float g_probe[MAXN * 96];  // dead scratch for the ncu probe launch
__device__ int   g_src[MAXE];
__device__ int   g_dst[MAXE];
__device__ int   g_ssrc[MAXE];        // src ids sorted by dst (CSR payload)
__device__ int   g_cnt[MAXN];         // in-degree histogram
__device__ int   g_rs [MAXN + 1];     // CSR row starts
__device__ int   g_cur[MAXN];         // scatter cursors
__device__ int   g_bsum[128];
__device__ int   g_boff[128];
__device__ int   g_is64;

// ---------------- asm helpers -------------------------------------------------
__device__ __forceinline__ void ffma2(ull& acc, ull a, ull b) {
    asm("fma.rn.f32x2 %0, %1, %2, %0;" : "+l"(acc) : "l"(a), "l"(b));
}
__device__ __forceinline__ ull pack2(float x, float y) {
    ull r; asm("mov.b64 %0, {%1, %2};" : "=l"(r) : "f"(x), "f"(y)); return r;
}
__device__ __forceinline__ float2 unpack2(ull v) {
    float2 r; asm("mov.b64 {%0, %1}, %2;" : "=f"(r.x), "=f"(r.y) : "l"(v)); return r;
}
__device__ __forceinline__ float ex2(float v) {
    float r; asm("ex2.approx.ftz.f32 %0, %1;" : "=f"(r) : "f"(v)); return r;
}

// ---------------- init: zero histogram + dtype detect -------------------------
// Detect int64 vs int32 edge_index: node ids < 2^17, so int64 => odd words 0.
__global__ void k_init(const int* __restrict__ p, int n) {
    int i = blockIdx.x * blockDim.x + threadIdx.x;
    if (i < n) g_cnt[i] = 0;
    if (i == 0) {
        int acc = 0;
#pragma unroll
        for (int j = 1; j < 64; j += 2) acc |= p[j];
        g_is64 = (acc == 0) ? 1 : 0;
    }
}

__global__ void k_edges(const void* __restrict__ ei, int E) {
    int i = blockIdx.x * blockDim.x + threadIdx.x;
    if (i >= E) return;
    int s, d;
    if (g_is64) {
        const long long* p = (const long long*)ei;
        s = (int)p[i]; d = (int)p[E + i];
    } else {
        const int* p = (const int*)ei;
        s = p[i]; d = p[E + i];
    }
    g_src[i] = s;
    g_dst[i] = d;
    atomicAdd(&g_cnt[d], 1);
}

// ---------------- scan (3-kernel exclusive prefix sum over g_cnt) ------------

__global__ void k_scan1(int n) {
    __shared__ int tmp[1024];
    int tid = threadIdx.x;
    int i = blockIdx.x * 1024 + tid;
    int v = (i < n) ? g_cnt[i] : 0;
    tmp[tid] = v;
    __syncthreads();
#pragma unroll
    for (int o = 1; o < 1024; o <<= 1) {
        int t = (tid >= o) ? tmp[tid - o] : 0;
        __syncthreads();
        tmp[tid] += t;
        __syncthreads();
    }
    if (i < n) g_rs[i] = tmp[tid] - v;         // block-local exclusive
    if (tid == 1023) g_bsum[blockIdx.x] = tmp[tid];
}

__global__ void k_scan2(int nb) {
    __shared__ int tmp[128];
    int tid = threadIdx.x;
    int v = (tid < nb) ? g_bsum[tid] : 0;
    tmp[tid] = v;
    __syncthreads();
#pragma unroll
    for (int o = 1; o < 128; o <<= 1) {
        int t = (tid >= o) ? tmp[tid - o] : 0;
        __syncthreads();
        tmp[tid] += t;
        __syncthreads();
    }
    if (tid < nb) g_boff[tid] = tmp[tid] - v;  // exclusive block offsets
}

__global__ void k_scan3(int n, int E) {
    int i = blockIdx.x * blockDim.x + threadIdx.x;
    if (i < n) {
        int r = g_rs[i] + g_boff[i >> 10];
        g_rs[i] = r;
        g_cur[i] = r;
    }
    if (i == 0) g_rs[n] = E;
}

__global__ void k_scatter(int E) {
    int i = blockIdx.x * blockDim.x + threadIdx.x;
    if (i >= E) return;
    int d = g_dst[i];
    int pos = atomicAdd(&g_cur[d], 1);
    g_ssrc[pos] = g_src[i];
}

// ---------------- node transforms --------------------------------------------

// h0 = relu(x @ W0) : [n,128]@[128,16]. Shared-staged, float4 global loads.
__global__ void __launch_bounds__(256)
k_lin0(const float* __restrict__ x, const float* __restrict__ W0, int n) {
    __shared__ float sx[16 * 128];   // 16 rows of x
    __shared__ float sw[128 * 16];   // W0
    int tid = threadIdx.x;
    int row0 = blockIdx.x * 16;
    for (int i = tid; i < 512; i += 256)
        ((float4*)sw)[i] = ((const float4*)W0)[i];
    for (int i = tid; i < 512; i += 256) {
        int r = i >> 5;                // row within tile
        int row = row0 + r;
        float4 v = make_float4(0.f, 0.f, 0.f, 0.f);
        if (row < n) v = ((const float4*)x)[row * 32 + (i & 31)];
        ((float4*)sx)[i] = v;
    }
    __syncthreads();
    int r = tid >> 4, c = tid & 15;
    const float4* sxr = (const float4*)(sx + r * 128);
    float acc = 0.f;
#pragma unroll
    for (int k4 = 0; k4 < 32; k4++) {
        float4 h = sxr[k4];
        acc = fmaf(h.x, sw[(4 * k4 + 0) * 16 + c], acc);
        acc = fmaf(h.y, sw[(4 * k4 + 1) * 16 + c], acc);
        acc = fmaf(h.z, sw[(4 * k4 + 2) * 16 + c], acc);
        acc = fmaf(h.w, sw[(4 * k4 + 3) * 16 + c], acc);
    }
    int row = row0 + r;
    if (row < n) g_h0[row * 16 + c] = fmaxf(acc, 0.f);
}

// layer-1 transforms: weights in registers (one output column per thread),
// h rows staged in shared (broadcast reads). 64 rows per block.
// Weight loads Wl[k*96+c]: consecutive c across lanes => fully coalesced.
__global__ void __launch_bounds__(384)
k_node1(const float* __restrict__ Wl, const float* __restrict__ bl,
        const float* __restrict__ Wr, const float* __restrict__ br,
        const float* __restrict__ Wf, const float* __restrict__ bf,
        const float* __restrict__ b1, int n) {
    __shared__ float sh[64 * 16];
    int c = threadIdx.x, ty = threadIdx.y;
    int tid = ty * 96 + c;
    int row0 = blockIdx.x * 64;
    float wl[16], wr[16], wf[16];
#pragma unroll
    for (int k = 0; k < 16; k++) {
        wl[k] = Wl[k * 96 + c];
        wr[k] = Wr[k * 96 + c];
        wf[k] = Wf[k * 96 + c];
    }
    float cbl = bl[c], cbr = br[c], cbf = bf[c] + b1[c];
    for (int i = tid; i < 1024; i += 384) {
        int r = i >> 4, k = i & 15;
        int row = row0 + r;
        sh[i] = (row < n) ? g_h0[row * 16 + k] : 0.f;
    }
    __syncthreads();
    for (int r = ty; r < 64; r += 4) {
        int row = row0 + r;
        if (row >= n) continue;
        float a0 = cbl, a1 = cbr, a2 = cbf;
#pragma unroll
        for (int k = 0; k < 16; k++) {
            float h = sh[r * 16 + k];
            a0 = fmaf(h, wl[k], a0);
            a1 = fmaf(h, wr[k], a1);
            a2 = fmaf(h, wf[k], a2);
        }
        g_hl[row * 96 + c] = a0;
        g_hr[row * 96 + c] = a1;
        g_acc[row * 96 + c] = a2;
    }
}

// layer-2 transforms via packed f32x2 FMA (FFMA2): rows in pairs, K=96 in 6
// chunks. Weights loaded DIRECT from W (consecutive c across lanes = coalesced).
// sh transposed [k][r] stride 34 (aligned LDS.64, broadcast/conflict-free).
__global__ void __launch_bounds__(384, 1)
k_node2(const float* __restrict__ Wl, const float* __restrict__ bl,
        const float* __restrict__ Wr, const float* __restrict__ br,
        const float* __restrict__ Wo, const float* __restrict__ bo,
        const float* __restrict__ b2, float* __restrict__ out, int n) {
    __shared__ float sh[16 * 34];
    int c = threadIdx.x, ty = threadIdx.y;
    int tid = ty * 96 + c;
    int row0 = blockIdx.x * 32;
    ull a0[4], a1[4], a2[4];
    float ibl = bl[c], ibr = br[c], ibo = bo[c] + b2[c];
#pragma unroll
    for (int jp = 0; jp < 4; jp++) {
        a0[jp] = pack2(ibl, ibl);
        a1[jp] = pack2(ibr, ibr);
        a2[jp] = pack2(ibo, ibo);
    }
    for (int kt = 0; kt < 6; kt++) {
        float wl[16], wr[16], wo[16];
#pragma unroll
        for (int k = 0; k < 16; k++) {
            wl[k] = Wl[(kt * 16 + k) * 96 + c];
            wr[k] = Wr[(kt * 16 + k) * 96 + c];
            wo[k] = Wo[(kt * 16 + k) * 96 + c];
        }
        for (int i = tid; i < 512; i += 384) {
            int k = i & 15, r = i >> 4;
            int row = row0 + r;
            float v = (row < n) ? g_acc[row * 96 + kt * 16 + k] : 0.f;
            sh[k * 34 + r] = fmaxf(v, 0.f);   // relu(h1), transposed
        }
        __syncthreads();
#pragma unroll
        for (int k = 0; k < 16; k++) {
            ull wl2 = pack2(wl[k], wl[k]);
            ull wr2 = pack2(wr[k], wr[k]);
            ull wo2 = pack2(wo[k], wo[k]);
#pragma unroll
            for (int jp = 0; jp < 4; jp++) {
                int p = ty + 4 * jp;
                ull h2 = *(const ull*)&sh[k * 34 + 2 * p];
                ffma2(a0[jp], h2, wl2);
                ffma2(a1[jp], h2, wr2);
                ffma2(a2[jp], h2, wo2);
            }
        }
        __syncthreads();
    }
#pragma unroll
    for (int jp = 0; jp < 4; jp++) {
        int p = ty + 4 * jp;
        float2 v0 = unpack2(a0[jp]);
        float2 v1 = unpack2(a1[jp]);
        float2 v2 = unpack2(a2[jp]);
        int ra = row0 + 2 * p, rb = ra + 1;
        if (ra < n) {
            g_hl[ra * 96 + c] = v0.x; g_hr[ra * 96 + c] = v1.x; out[ra * 96 + c] = v2.x;
        }
        if (rb < n) {
            g_hl[rb * 96 + c] = v0.y; g_hr[rb * 96 + c] = v1.y; out[rb * 96 + c] = v2.y;
        }
    }
}

// ---------------- fused GATv2 edge phase: warp per node, 4 edges x 8 lanes ---
// Lane = 8*grp + g. Group grp handles edge (base+grp); lane owns channels
// {4g..4g+3} of each head (float4). One SHFL reduces all 4 edges at once.
// mode: 0 = write ext_out, 1 = write g_acc, 2 = PROBE (write g_probe scratch).
// Probe safety: device globals are zero-initialized, so on the first call
// (before CSR is built) g_rs is all zeros -> beg==end -> probe does nothing;
// on graph replays the CSR from the prior call is valid and the probe runs
// the real code path. Probe output is never read.
__global__ void __launch_bounds__(256)
k_gat(const float* __restrict__ att, float* __restrict__ ext_out,
      int mode, int n) {
    int v = (blockIdx.x * blockDim.x + threadIdx.x) >> 5;
    int lane = threadIdx.x & 31;
    if (v >= n) return;
    float* out = (mode == 1) ? g_acc : ((mode == 2) ? g_probe : ext_out);
    int grp = lane >> 3, g = lane & 7;
    int beg = g_rs[v], end = g_rs[v + 1];
    const float L2E = 1.44269504088896340736f;

    const float4* attv = (const float4*)att;
    float4 at0 = attv[g], at1 = attv[8 + g], at2 = attv[16 + g];
    at0.x *= L2E; at0.y *= L2E; at0.z *= L2E; at0.w *= L2E;
    at1.x *= L2E; at1.y *= L2E; at1.z *= L2E; at1.w *= L2E;
    at2.x *= L2E; at2.y *= L2E; at2.z *= L2E; at2.w *= L2E;

    const float4* hrv = (const float4*)(g_hr + (size_t)v * 96);
    float4 hr0 = hrv[g], hr1 = hrv[8 + g], hr2 = hrv[16 + g];

    float4 ac0 = make_float4(0.f, 0.f, 0.f, 0.f);
    float4 ac1 = ac0, ac2 = ac0;
    float den0 = 0.f, den1 = 0.f, den2 = 0.f;

#pragma unroll 4
    for (int base = beg; base < end; base += 4) {
        int e = base + grp;
        bool valid = (e < end);
        int ee = valid ? e : end - 1;
        int s = g_ssrc[ee];
        const float4* hlv = (const float4*)(g_hl + (size_t)s * 96);
        float4 h0 = hlv[g], h1 = hlv[8 + g], h2 = hlv[16 + g];

        float s0, s1, s2, t;
        t = h0.x + hr0.x; t = fmaxf(t, NEG * t); s0 = at0.x * t;
        t = h0.y + hr0.y; t = fmaxf(t, NEG * t); s0 = fmaf(at0.y, t, s0);
        t = h0.z + hr0.z; t = fmaxf(t, NEG * t); s0 = fmaf(at0.z, t, s0);
        t = h0.w + hr0.w; t = fmaxf(t, NEG * t); s0 = fmaf(at0.w, t, s0);
        t = h1.x + hr1.x; t = fmaxf(t, NEG * t); s1 = at1.x * t;
        t = h1.y + hr1.y; t = fmaxf(t, NEG * t); s1 = fmaf(at1.y, t, s1);
        t = h1.z + hr1.z; t = fmaxf(t, NEG * t); s1 = fmaf(at1.z, t, s1);
        t = h1.w + hr1.w; t = fmaxf(t, NEG * t); s1 = fmaf(at1.w, t, s1);
        t = h2.x + hr2.x; t = fmaxf(t, NEG * t); s2 = at2.x * t;
        t = h2.y + hr2.y; t = fmaxf(t, NEG * t); s2 = fmaf(at2.y, t, s2);
        t = h2.z + hr2.z; t = fmaxf(t, NEG * t); s2 = fmaf(at2.z, t, s2);
        t = h2.w + hr2.w; t = fmaxf(t, NEG * t); s2 = fmaf(at2.w, t, s2);

#pragma unroll
        for (int o = 4; o; o >>= 1) {           // reduce within 8-lane group
            s0 += __shfl_xor_sync(0xffffffffu, s0, o);
            s1 += __shfl_xor_sync(0xffffffffu, s1, o);
            s2 += __shfl_xor_sync(0xffffffffu, s2, o);
        }
        float p0 = valid ? ex2(s0) : 0.f;
        float p1 = valid ? ex2(s1) : 0.f;
        float p2 = valid ? ex2(s2) : 0.f;
        den0 += p0; den1 += p1; den2 += p2;
        ac0.x = fmaf(p0, h0.x, ac0.x); ac0.y = fmaf(p0, h0.y, ac0.y);
        ac0.z = fmaf(p0, h0.z, ac0.z); ac0.w = fmaf(p0, h0.w, ac0.w);
        ac1.x = fmaf(p1, h1.x, ac1.x); ac1.y = fmaf(p1, h1.y, ac1.y);
        ac1.z = fmaf(p1, h1.z, ac1.z); ac1.w = fmaf(p1, h1.w, ac1.w);
        ac2.x = fmaf(p2, h2.x, ac2.x); ac2.y = fmaf(p2, h2.y, ac2.y);
        ac2.z = fmaf(p2, h2.z, ac2.z); ac2.w = fmaf(p2, h2.w, ac2.w);
    }

    // cross-group combine (once per node): sum over the 4 groups
#pragma unroll
    for (int o = 8; o <= 16; o <<= 1) {
        den0 += __shfl_xor_sync(0xffffffffu, den0, o);
        den1 += __shfl_xor_sync(0xffffffffu, den1, o);
        den2 += __shfl_xor_sync(0xffffffffu, den2, o);
        ac0.x += __shfl_xor_sync(0xffffffffu, ac0.x, o);
        ac0.y += __shfl_xor_sync(0xffffffffu, ac0.y, o);
        ac0.z += __shfl_xor_sync(0xffffffffu, ac0.z, o);
        ac0.w += __shfl_xor_sync(0xffffffffu, ac0.w, o);
        ac1.x += __shfl_xor_sync(0xffffffffu, ac1.x, o);
        ac1.y += __shfl_xor_sync(0xffffffffu, ac1.y, o);
        ac1.z += __shfl_xor_sync(0xffffffffu, ac1.z, o);
        ac1.w += __shfl_xor_sync(0xffffffffu, ac1.w, o);
        ac2.x += __shfl_xor_sync(0xffffffffu, ac2.x, o);
        ac2.y += __shfl_xor_sync(0xffffffffu, ac2.y, o);
        ac2.z += __shfl_xor_sync(0xffffffffu, ac2.z, o);
        ac2.w += __shfl_xor_sync(0xffffffffu, ac2.w, o);
    }

    if (grp == 0) {
        float r0 = __fdividef(1.f, den0 + 1e-16f);
        float r1 = __fdividef(1.f, den1 + 1e-16f);
        float r2 = __fdividef(1.f, den2 + 1e-16f);
        float4* orow = (float4*)(out + (size_t)v * 96);
        float4 o0 = orow[g], o1 = orow[8 + g], o2 = orow[16 + g];
        o0.x = fmaf(ac0.x, r0, o0.x); o0.y = fmaf(ac0.y, r0, o0.y);
        o0.z = fmaf(ac0.z, r0, o0.z); o0.w = fmaf(ac0.w, r0, o0.w);
        o1.x = fmaf(ac1.x, r1, o1.x); o1.y = fmaf(ac1.y, r1, o1.y);
        o1.z = fmaf(ac1.z, r1, o1.z); o1.w = fmaf(ac1.w, r1, o1.w);
        o2.x = fmaf(ac2.x, r2, o2.x); o2.y = fmaf(ac2.y, r2, o2.y);
        o2.z = fmaf(ac2.z, r2, o2.z); o2.w = fmaf(ac2.w, r2, o2.w);
        orow[g] = o0; orow[8 + g] = o1; orow[16 + g] = o2;
    }
}

// ---------------- launch ------------------------------------------------------

extern "C" void kernel_launch(void* const* d_in, const int* in_sizes, int n_in,
                              void* d_out, int out_size) {
    const float* x     = (const float*)d_in[0];
    const void*  ei    = (const void*)d_in[1];
    const float* W0    = (const float*)d_in[2];
    const float* Wl1   = (const float*)d_in[3];
    const float* bl1   = (const float*)d_in[4];
    const float* Wr1   = (const float*)d_in[5];
    const float* br1   = (const float*)d_in[6];
    const float* att1  = (const float*)d_in[7];
    const float* b1    = (const float*)d_in[8];
    const float* Wf    = (const float*)d_in[9];
    const float* bf    = (const float*)d_in[10];
    const float* Wl2   = (const float*)d_in[11];
    const float* bl2   = (const float*)d_in[12];
    const float* Wr2   = (const float*)d_in[13];
    const float* br2   = (const float*)d_in[14];
    const float* att2  = (const float*)d_in[15];
    const float* b2    = (const float*)d_in[16];
    const float* Wlast = (const float*)d_in[17];
    const float* blast = (const float*)d_in[18];
    float* out = (float*)d_out;

    int n = in_sizes[0] / 128;
    int E = in_sizes[1] / 2;
    int NB = (n + 1023) / 1024;          // scan blocks (<=128)
    int nprobe = n / 8;

    // ncu captures launch idx 3 -> put a 1/8-scale k_gat PROBE there.
    // On the correctness-run call the CSR globals are still zero-initialized
    // (no work); on timed replays it profiles the real gat inner loop.
    k_init<<<(n + 255) / 256, 256>>>((const int*)ei, n);
    k_edges<<<(E + 255) / 256, 256>>>(ei, E);
    k_lin0<<<(n + 15) / 16, 256>>>(x, W0, n);
    k_gat<<<(nprobe + 7) / 8, 256>>>(att1, out, 2, nprobe);   // PROBE (idx 3)
    k_node1<<<(n + 63) / 64, dim3(96, 4)>>>(Wl1, bl1, Wr1, br1, Wf, bf, b1, n);
    k_scan1<<<NB, 1024>>>(n);
    k_scan2<<<1, 128>>>(NB);
    k_scan3<<<(n + 255) / 256, 256>>>(n, E);
    k_scatter<<<(E + 255) / 256, 256>>>(E);

    // ---- layer 1 edge phase (into g_acc which holds skip + b1) ----
    k_gat<<<(n + 7) / 8, 256>>>(att1, out, 1, n);

    // ---- layer 2 node transforms (relu fused on load; out gets skip + b2) ----
    k_node2<<<(n + 31) / 32, dim3(96, 4)>>>(Wl2, bl2, Wr2, br2, Wlast, blast, b2, out, n);

    // ---- layer 2 edge phase (into d_out) ----
    k_gat<<<(n + 7) / 8, 256>>>(att2, out, 0, n);
}

// round 12
// speedup vs baseline: 1.0311x; 1.0311x over previous
#include <cuda_runtime.h>

#define MAXN 100000
#define MAXE 1600000
#define NEG 0.2f

typedef unsigned long long ull;

// ---------------- scratch (static device globals; no allocation) -------------
__device__ float g_h0 [MAXN * 16];    // relu(x@W0)
__device__ float g_hl [MAXN * 96];    // source transform (current layer)
__device__ float g_hr [MAXN * 96];    // target transform (current layer)
__device__ float g_acc[MAXN * 96];    // layer-1 accumulator = skip + b1 + msgs
__device__ float g_probe[MAXN * 96];  // dead scratch for the ncu probe launch
__device__ int   g_src[MAXE];
__device__ int   g_dst[MAXE];
__device__ int   g_ssrc[MAXE];        // src ids sorted by dst (CSR payload)
__device__ int   g_cnt[MAXN];         // in-degree histogram
__device__ int   g_rs [MAXN + 1];     // CSR row starts
__device__ int   g_cur[MAXN];         // scatter cursors
__device__ int   g_bsum[128];
__device__ int   g_boff[128];
__device__ int   g_is64;

// ---------------- asm helpers -------------------------------------------------
__device__ __forceinline__ void ffma2(ull& acc, ull a, ull b) {
    asm("fma.rn.f32x2 %0, %1, %2, %0;" : "+l"(acc) : "l"(a), "l"(b));
}
__device__ __forceinline__ ull pack2(float x, float y) {
    ull r; asm("mov.b64 %0, {%1, %2};" : "=l"(r) : "f"(x), "f"(y)); return r;
}
__device__ __forceinline__ float2 unpack2(ull v) {
    float2 r; asm("mov.b64 {%0, %1}, %2;" : "=f"(r.x), "=f"(r.y) : "l"(v)); return r;
}
__device__ __forceinline__ float ex2(float v) {
    float r; asm("ex2.approx.ftz.f32 %0, %1;" : "=f"(r) : "f"(v)); return r;
}

// ---------------- init: zero histogram + dtype detect -------------------------
// Detect int64 vs int32 edge_index: node ids < 2^17, so int64 => odd words 0.
__global__ void k_init(const int* __restrict__ p, int n) {
    int i = blockIdx.x * blockDim.x + threadIdx.x;
    if (i < n) g_cnt[i] = 0;
    if (i == 0) {
        int acc = 0;
#pragma unroll
        for (int j = 1; j < 64; j += 2) acc |= p[j];
        g_is64 = (acc == 0) ? 1 : 0;
    }
}

__global__ void k_edges(const void* __restrict__ ei, int E) {
    int i = blockIdx.x * blockDim.x + threadIdx.x;
    if (i >= E) return;
    int s, d;
    if (g_is64) {
        const long long* p = (const long long*)ei;
        s = (int)p[i]; d = (int)p[E + i];
    } else {
        const int* p = (const int*)ei;
        s = p[i]; d = p[E + i];
    }
    g_src[i] = s;
    g_dst[i] = d;
    atomicAdd(&g_cnt[d], 1);
}

// ---------------- scan (3-kernel exclusive prefix sum over g_cnt) ------------

__global__ void k_scan1(int n) {
    __shared__ int tmp[1024];
    int tid = threadIdx.x;
    int i = blockIdx.x * 1024 + tid;
    int v = (i < n) ? g_cnt[i] : 0;
    tmp[tid] = v;
    __syncthreads();
#pragma unroll
    for (int o = 1; o < 1024; o <<= 1) {
        int t = (tid >= o) ? tmp[tid - o] : 0;
        __syncthreads();
        tmp[tid] += t;
        __syncthreads();
    }
    if (i < n) g_rs[i] = tmp[tid] - v;         // block-local exclusive
    if (tid == 1023) g_bsum[blockIdx.x] = tmp[tid];
}

__global__ void k_scan2(int nb) {
    __shared__ int tmp[128];
    int tid = threadIdx.x;
    int v = (tid < nb) ? g_bsum[tid] : 0;
    tmp[tid] = v;
    __syncthreads();
#pragma unroll
    for (int o = 1; o < 128; o <<= 1) {
        int t = (tid >= o) ? tmp[tid - o] : 0;
        __syncthreads();
        tmp[tid] += t;
        __syncthreads();
    }
    if (tid < nb) g_boff[tid] = tmp[tid] - v;  // exclusive block offsets
}

__global__ void k_scan3(int n, int E) {
    int i = blockIdx.x * blockDim.x + threadIdx.x;
    if (i < n) {
        int r = g_rs[i] + g_boff[i >> 10];
        g_rs[i] = r;
        g_cur[i] = r;
    }
    if (i == 0) g_rs[n] = E;
}

__global__ void k_scatter(int E) {
    int i = blockIdx.x * blockDim.x + threadIdx.x;
    if (i >= E) return;
    int d = g_dst[i];
    int pos = atomicAdd(&g_cur[d], 1);
    g_ssrc[pos] = g_src[i];
}

// ---------------- node transforms --------------------------------------------

// h0 = relu(x @ W0) : [n,128]@[128,16]. Shared-staged, float4 global loads.
__global__ void __launch_bounds__(256)
k_lin0(const float* __restrict__ x, const float* __restrict__ W0, int n) {
    __shared__ float sx[16 * 128];   // 16 rows of x
    __shared__ float sw[128 * 16];   // W0
    int tid = threadIdx.x;
    int row0 = blockIdx.x * 16;
    for (int i = tid; i < 512; i += 256)
        ((float4*)sw)[i] = ((const float4*)W0)[i];
    for (int i = tid; i < 512; i += 256) {
        int r = i >> 5;                // row within tile
        int row = row0 + r;
        float4 v = make_float4(0.f, 0.f, 0.f, 0.f);
        if (row < n) v = ((const float4*)x)[row * 32 + (i & 31)];
        ((float4*)sx)[i] = v;
    }
    __syncthreads();
    int r = tid >> 4, c = tid & 15;
    const float4* sxr = (const float4*)(sx + r * 128);
    float acc = 0.f;
#pragma unroll
    for (int k4 = 0; k4 < 32; k4++) {
        float4 h = sxr[k4];
        acc = fmaf(h.x, sw[(4 * k4 + 0) * 16 + c], acc);
        acc = fmaf(h.y, sw[(4 * k4 + 1) * 16 + c], acc);
        acc = fmaf(h.z, sw[(4 * k4 + 2) * 16 + c], acc);
        acc = fmaf(h.w, sw[(4 * k4 + 3) * 16 + c], acc);
    }
    int row = row0 + r;
    if (row < n) g_h0[row * 16 + c] = fmaxf(acc, 0.f);
}

// layer-1 transforms: weights in registers (one output column per thread),
// h rows staged in shared (broadcast reads). 64 rows per block.
__global__ void __launch_bounds__(384)
k_node1(const float* __restrict__ Wl, const float* __restrict__ bl,
        const float* __restrict__ Wr, const float* __restrict__ br,
        const float* __restrict__ Wf, const float* __restrict__ bf,
        const float* __restrict__ b1, int n) {
    __shared__ float sh[64 * 16];
    int c = threadIdx.x, ty = threadIdx.y;
    int tid = ty * 96 + c;
    int row0 = blockIdx.x * 64;
    float wl[16], wr[16], wf[16];
#pragma unroll
    for (int k = 0; k < 16; k++) {
        wl[k] = Wl[k * 96 + c];
        wr[k] = Wr[k * 96 + c];
        wf[k] = Wf[k * 96 + c];
    }
    float cbl = bl[c], cbr = br[c], cbf = bf[c] + b1[c];
    for (int i = tid; i < 1024; i += 384) {
        int r = i >> 4, k = i & 15;
        int row = row0 + r;
        sh[i] = (row < n) ? g_h0[row * 16 + k] : 0.f;
    }
    __syncthreads();
    for (int r = ty; r < 64; r += 4) {
        int row = row0 + r;
        if (row >= n) continue;
        float a0 = cbl, a1 = cbr, a2 = cbf;
#pragma unroll
        for (int k = 0; k < 16; k++) {
            float h = sh[r * 16 + k];
            a0 = fmaf(h, wl[k], a0);
            a1 = fmaf(h, wr[k], a1);
            a2 = fmaf(h, wf[k], a2);
        }
        g_hl[row * 96 + c] = a0;
        g_hr[row * 96 + c] = a1;
        g_acc[row * 96 + c] = a2;
    }
}

// layer-2 transforms via packed f32x2 FMA (FFMA2): rows in pairs, K=96 in 6
// chunks. Weights loaded DIRECT from W (consecutive c across lanes = coalesced).
// sh transposed [k][r] stride 34 (aligned LDS.64, conflict-free).
// probe!=0: ALL writes go to g_probe scratch (ncu measurement launch).
__global__ void __launch_bounds__(384, 1)
k_node2(const float* __restrict__ Wl, const float* __restrict__ bl,
        const float* __restrict__ Wr, const float* __restrict__ br,
        const float* __restrict__ Wo, const float* __restrict__ bo,
        const float* __restrict__ b2, float* __restrict__ out, int probe, int n) {
    __shared__ float sh[16 * 34];
    int c = threadIdx.x, ty = threadIdx.y;
    int tid = ty * 96 + c;
    int row0 = blockIdx.x * 32;
    float* ohl = probe ? g_probe : g_hl;
    float* ohr = probe ? g_probe : g_hr;
    float* oo  = probe ? g_probe : out;
    ull a0[4], a1[4], a2[4];
    float ibl = bl[c], ibr = br[c], ibo = bo[c] + b2[c];
#pragma unroll
    for (int jp = 0; jp < 4; jp++) {
        a0[jp] = pack2(ibl, ibl);
        a1[jp] = pack2(ibr, ibr);
        a2[jp] = pack2(ibo, ibo);
    }
    for (int kt = 0; kt < 6; kt++) {
        float wl[16], wr[16], wo[16];
#pragma unroll
        for (int k = 0; k < 16; k++) {
            wl[k] = Wl[(kt * 16 + k) * 96 + c];
            wr[k] = Wr[(kt * 16 + k) * 96 + c];
            wo[k] = Wo[(kt * 16 + k) * 96 + c];
        }
        for (int i = tid; i < 512; i += 384) {
            int k = i & 15, r = i >> 4;
            int row = row0 + r;
            float v = (row < n) ? g_acc[row * 96 + kt * 16 + k] : 0.f;
            sh[k * 34 + r] = fmaxf(v, 0.f);   // relu(h1), transposed
        }
        __syncthreads();
#pragma unroll
        for (int k = 0; k < 16; k++) {
            ull wl2 = pack2(wl[k], wl[k]);
            ull wr2 = pack2(wr[k], wr[k]);
            ull wo2 = pack2(wo[k], wo[k]);
#pragma unroll
            for (int jp = 0; jp < 4; jp++) {
                int p = ty + 4 * jp;
                ull h2 = *(const ull*)&sh[k * 34 + 2 * p];
                ffma2(a0[jp], h2, wl2);
                ffma2(a1[jp], h2, wr2);
                ffma2(a2[jp], h2, wo2);
            }
        }
        __syncthreads();
    }
#pragma unroll
    for (int jp = 0; jp < 4; jp++) {
        int p = ty + 4 * jp;
        float2 v0 = unpack2(a0[jp]);
        float2 v1 = unpack2(a1[jp]);
        float2 v2 = unpack2(a2[jp]);
        int ra = row0 + 2 * p, rb = ra + 1;
        if (ra < n) {
            ohl[ra * 96 + c] = v0.x; ohr[ra * 96 + c] = v1.x; oo[ra * 96 + c] = v2.x;
        }
        if (rb < n) {
            ohl[rb * 96 + c] = v0.y; ohr[rb * 96 + c] = v1.y; oo[rb * 96 + c] = v2.y;
        }
    }
}

// ---------------- fused GATv2 edge phase: warp per node, 4 edges x 8 lanes ---
// Lane = 8*grp + g. Group grp handles edge (base+grp); lane owns channels
// {4g..4g+3} of each head (float4). One SHFL reduces all 4 edges at once.
// mode: 0 = write ext_out, 1 = write g_acc.
// launch_bounds(256,4): cap 64 regs -> 4 blocks/SM (32 warps) since the R11
// probe showed latency-bound (occ 31.5%, issue 26%, all pipes idle).
// NOTE: internal target (g_acc) resolved in DEVICE code (host symbol != dev ptr).
__global__ void __launch_bounds__(256, 4)
k_gat(const float* __restrict__ att, float* __restrict__ ext_out,
      int mode, int n) {
    int v = (blockIdx.x * blockDim.x + threadIdx.x) >> 5;
    int lane = threadIdx.x & 31;
    if (v >= n) return;
    float* out = (mode == 1) ? g_acc : ext_out;
    int grp = lane >> 3, g = lane & 7;
    int beg = g_rs[v], end = g_rs[v + 1];
    const float L2E = 1.44269504088896340736f;

    const float4* attv = (const float4*)att;
    float4 at0 = attv[g], at1 = attv[8 + g], at2 = attv[16 + g];
    at0.x *= L2E; at0.y *= L2E; at0.z *= L2E; at0.w *= L2E;
    at1.x *= L2E; at1.y *= L2E; at1.z *= L2E; at1.w *= L2E;
    at2.x *= L2E; at2.y *= L2E; at2.z *= L2E; at2.w *= L2E;

    const float4* hrv = (const float4*)(g_hr + (size_t)v * 96);
    float4 hr0 = hrv[g], hr1 = hrv[8 + g], hr2 = hrv[16 + g];

    float4 ac0 = make_float4(0.f, 0.f, 0.f, 0.f);
    float4 ac1 = ac0, ac2 = ac0;
    float den0 = 0.f, den1 = 0.f, den2 = 0.f;

#pragma unroll 2
    for (int base = beg; base < end; base += 4) {
        int e = base + grp;
        bool valid = (e < end);
        int ee = valid ? e : end - 1;
        int s = g_ssrc[ee];
        const float4* hlv = (const float4*)(g_hl + (size_t)s * 96);
        float4 h0 = hlv[g], h1 = hlv[8 + g], h2 = hlv[16 + g];

        float s0, s1, s2, t;
        t = h0.x + hr0.x; t = fmaxf(t, NEG * t); s0 = at0.x * t;
        t = h0.y + hr0.y; t = fmaxf(t, NEG * t); s0 = fmaf(at0.y, t, s0);
        t = h0.z + hr0.z; t = fmaxf(t, NEG * t); s0 = fmaf(at0.z, t, s0);
        t = h0.w + hr0.w; t = fmaxf(t, NEG * t); s0 = fmaf(at0.w, t, s0);
        t = h1.x + hr1.x; t = fmaxf(t, NEG * t); s1 = at1.x * t;
        t = h1.y + hr1.y; t = fmaxf(t, NEG * t); s1 = fmaf(at1.y, t, s1);
        t = h1.z + hr1.z; t = fmaxf(t, NEG * t); s1 = fmaf(at1.z, t, s1);
        t = h1.w + hr1.w; t = fmaxf(t, NEG * t); s1 = fmaf(at1.w, t, s1);
        t = h2.x + hr2.x; t = fmaxf(t, NEG * t); s2 = at2.x * t;
        t = h2.y + hr2.y; t = fmaxf(t, NEG * t); s2 = fmaf(at2.y, t, s2);
        t = h2.z + hr2.z; t = fmaxf(t, NEG * t); s2 = fmaf(at2.z, t, s2);
        t = h2.w + hr2.w; t = fmaxf(t, NEG * t); s2 = fmaf(at2.w, t, s2);

#pragma unroll
        for (int o = 4; o; o >>= 1) {           // reduce within 8-lane group
            s0 += __shfl_xor_sync(0xffffffffu, s0, o);
            s1 += __shfl_xor_sync(0xffffffffu, s1, o);
            s2 += __shfl_xor_sync(0xffffffffu, s2, o);
        }
        float p0 = valid ? ex2(s0) : 0.f;
        float p1 = valid ? ex2(s1) : 0.f;
        float p2 = valid ? ex2(s2) : 0.f;
        den0 += p0; den1 += p1; den2 += p2;
        ac0.x = fmaf(p0, h0.x, ac0.x); ac0.y = fmaf(p0, h0.y, ac0.y);
        ac0.z = fmaf(p0, h0.z, ac0.z); ac0.w = fmaf(p0, h0.w, ac0.w);
        ac1.x = fmaf(p1, h1.x, ac1.x); ac1.y = fmaf(p1, h1.y, ac1.y);
        ac1.z = fmaf(p1, h1.z, ac1.z); ac1.w = fmaf(p1, h1.w, ac1.w);
        ac2.x = fmaf(p2, h2.x, ac2.x); ac2.y = fmaf(p2, h2.y, ac2.y);
        ac2.z = fmaf(p2, h2.z, ac2.z); ac2.w = fmaf(p2, h2.w, ac2.w);
    }

    // cross-group combine (once per node): sum over the 4 groups
#pragma unroll
    for (int o = 8; o <= 16; o <<= 1) {
        den0 += __shfl_xor_sync(0xffffffffu, den0, o);
        den1 += __shfl_xor_sync(0xffffffffu, den1, o);
        den2 += __shfl_xor_sync(0xffffffffu, den2, o);
        ac0.x += __shfl_xor_sync(0xffffffffu, ac0.x, o);
        ac0.y += __shfl_xor_sync(0xffffffffu, ac0.y, o);
        ac0.z += __shfl_xor_sync(0xffffffffu, ac0.z, o);
        ac0.w += __shfl_xor_sync(0xffffffffu, ac0.w, o);
        ac1.x += __shfl_xor_sync(0xffffffffu, ac1.x, o);
        ac1.y += __shfl_xor_sync(0xffffffffu, ac1.y, o);
        ac1.z += __shfl_xor_sync(0xffffffffu, ac1.z, o);
        ac1.w += __shfl_xor_sync(0xffffffffu, ac1.w, o);
        ac2.x += __shfl_xor_sync(0xffffffffu, ac2.x, o);
        ac2.y += __shfl_xor_sync(0xffffffffu, ac2.y, o);
        ac2.z += __shfl_xor_sync(0xffffffffu, ac2.z, o);
        ac2.w += __shfl_xor_sync(0xffffffffu, ac2.w, o);
    }

    if (grp == 0) {
        float r0 = __fdividef(1.f, den0 + 1e-16f);
        float r1 = __fdividef(1.f, den1 + 1e-16f);
        float r2 = __fdividef(1.f, den2 + 1e-16f);
        float4* orow = (float4*)(out + (size_t)v * 96);
        float4 o0 = orow[g], o1 = orow[8 + g], o2 = orow[16 + g];
        o0.x = fmaf(ac0.x, r0, o0.x); o0.y = fmaf(ac0.y, r0, o0.y);
        o0.z = fmaf(ac0.z, r0, o0.z); o0.w = fmaf(ac0.w, r0, o0.w);
        o1.x = fmaf(ac1.x, r1, o1.x); o1.y = fmaf(ac1.y, r1, o1.y);
        o1.z = fmaf(ac1.z, r1, o1.z); o1.w = fmaf(ac1.w, r1, o1.w);
        o2.x = fmaf(ac2.x, r2, o2.x); o2.y = fmaf(ac2.y, r2, o2.y);
        o2.z = fmaf(ac2.z, r2, o2.z); o2.w = fmaf(ac2.w, r2, o2.w);
        orow[g] = o0; orow[8 + g] = o1; orow[16 + g] = o2;
    }
}

// ---------------- launch ------------------------------------------------------

extern "C" void kernel_launch(void* const* d_in, const int* in_sizes, int n_in,
                              void* d_out, int out_size) {
    const float* x     = (const float*)d_in[0];
    const void*  ei    = (const void*)d_in[1];
    const float* W0    = (const float*)d_in[2];
    const float* Wl1   = (const float*)d_in[3];
    const float* bl1   = (const float*)d_in[4];
    const float* Wr1   = (const float*)d_in[5];
    const float* br1   = (const float*)d_in[6];
    const float* att1  = (const float*)d_in[7];
    const float* b1    = (const float*)d_in[8];
    const float* Wf    = (const float*)d_in[9];
    const float* bf    = (const float*)d_in[10];
    const float* Wl2   = (const float*)d_in[11];
    const float* bl2   = (const float*)d_in[12];
    const float* Wr2   = (const float*)d_in[13];
    const float* br2   = (const float*)d_in[14];
    const float* att2  = (const float*)d_in[15];
    const float* b2    = (const float*)d_in[16];
    const float* Wlast = (const float*)d_in[17];
    const float* blast = (const float*)d_in[18];
    float* out = (float*)d_out;

    int n = in_sizes[0] / 128;
    int E = in_sizes[1] / 2;
    int NB = (n + 1023) / 1024;          // scan blocks (<=128)
    int nprobe = n / 8;

    // ncu captures launch idx 3 -> put a 1/8-scale k_node2 PROBE there.
    // Probe reads g_acc (deterministic across replays) and writes ONLY the
    // g_probe scratch, so correctness output is unaffected.
    k_init<<<(n + 255) / 256, 256>>>((const int*)ei, n);
    k_edges<<<(E + 255) / 256, 256>>>(ei, E);
    k_lin0<<<(n + 15) / 16, 256>>>(x, W0, n);
    k_node2<<<(nprobe + 31) / 32, dim3(96, 4)>>>(Wl2, bl2, Wr2, br2, Wlast, blast,
                                                 b2, out, 1, nprobe);  // PROBE (idx 3)
    k_node1<<<(n + 63) / 64, dim3(96, 4)>>>(Wl1, bl1, Wr1, br1, Wf, bf, b1, n);
    k_scan1<<<NB, 1024>>>(n);
    k_scan2<<<1, 128>>>(NB);
    k_scan3<<<(n + 255) / 256, 256>>>(n, E);
    k_scatter<<<(E + 255) / 256, 256>>>(E);

    // ---- layer 1 edge phase (into g_acc which holds skip + b1) ----
    k_gat<<<(n + 7) / 8, 256>>>(att1, out, 1, n);

    // ---- layer 2 node transforms (relu fused on load; out gets skip + b2) ----
    k_node2<<<(n + 31) / 32, dim3(96, 4)>>>(Wl2, bl2, Wr2, br2, Wlast, blast,
                                            b2, out, 0, n);

    // ---- layer 2 edge phase (into d_out) ----
    k_gat<<<(n + 7) / 8, 256>>>(att2, out, 0, n);
}

// round 13
// speedup vs baseline: 1.2094x; 1.1729x over previous
#include <cuda_runtime.h>

#define MAXN 100000
#define MAXE 1600000
#define NEG 0.2f

typedef unsigned long long ull;

// ---------------- scratch (static device globals; no allocation) -------------
__device__ float g_h0 [MAXN * 16];    // relu(x@W0)
__device__ float g_hl [MAXN * 96];    // source transform (current layer)
__device__ float g_hr [MAXN * 96];    // target transform (current layer)
__device__ float g_acc[MAXN * 96];    // layer-1 accumulator = skip + b1 + msgs
__device__ float g_probe[MAXN * 96];  // dead scratch for the ncu probe launch
__device__ int   g_src[MAXE];
__device__ int   g_dst[MAXE];
__device__ int   g_ssrc[MAXE];        // src ids sorted by dst (CSR payload)
__device__ int   g_cnt[MAXN];         // in-degree histogram
__device__ int   g_rs [MAXN + 1];     // CSR row starts
__device__ int   g_cur[MAXN];         // scatter cursors
__device__ int   g_bsum[128];
__device__ int   g_boff[128];
__device__ int   g_is64;

// ---------------- asm helpers -------------------------------------------------
__device__ __forceinline__ void ffma2(ull& acc, ull a, ull b) {
    asm("fma.rn.f32x2 %0, %1, %2, %0;" : "+l"(acc) : "l"(a), "l"(b));
}
__device__ __forceinline__ ull pack2(float x, float y) {
    ull r; asm("mov.b64 %0, {%1, %2};" : "=l"(r) : "f"(x), "f"(y)); return r;
}
__device__ __forceinline__ float2 unpack2(ull v) {
    float2 r; asm("mov.b64 {%0, %1}, %2;" : "=f"(r.x), "=f"(r.y) : "l"(v)); return r;
}
__device__ __forceinline__ float ex2(float v) {
    float r; asm("ex2.approx.ftz.f32 %0, %1;" : "=f"(r) : "f"(v)); return r;
}

// ---------------- init: zero histogram + dtype detect -------------------------
// Detect int64 vs int32 edge_index: node ids < 2^17, so int64 => odd words 0.
__global__ void k_init(const int* __restrict__ p, int n) {
    int i = blockIdx.x * blockDim.x + threadIdx.x;
    if (i < n) g_cnt[i] = 0;
    if (i == 0) {
        int acc = 0;
#pragma unroll
        for (int j = 1; j < 64; j += 2) acc |= p[j];
        g_is64 = (acc == 0) ? 1 : 0;
    }
}

__global__ void k_edges(const void* __restrict__ ei, int E) {
    int i = blockIdx.x * blockDim.x + threadIdx.x;
    if (i >= E) return;
    int s, d;
    if (g_is64) {
        const long long* p = (const long long*)ei;
        s = (int)p[i]; d = (int)p[E + i];
    } else {
        const int* p = (const int*)ei;
        s = p[i]; d = p[E + i];
    }
    g_src[i] = s;
    g_dst[i] = d;
    atomicAdd(&g_cnt[d], 1);
}

// ---------------- scan (3-kernel exclusive prefix sum over g_cnt) ------------

__global__ void k_scan1(int n) {
    __shared__ int tmp[1024];
    int tid = threadIdx.x;
    int i = blockIdx.x * 1024 + tid;
    int v = (i < n) ? g_cnt[i] : 0;
    tmp[tid] = v;
    __syncthreads();
#pragma unroll
    for (int o = 1; o < 1024; o <<= 1) {
        int t = (tid >= o) ? tmp[tid - o] : 0;
        __syncthreads();
        tmp[tid] += t;
        __syncthreads();
    }
    if (i < n) g_rs[i] = tmp[tid] - v;         // block-local exclusive
    if (tid == 1023) g_bsum[blockIdx.x] = tmp[tid];
}

__global__ void k_scan2(int nb) {
    __shared__ int tmp[128];
    int tid = threadIdx.x;
    int v = (tid < nb) ? g_bsum[tid] : 0;
    tmp[tid] = v;
    __syncthreads();
#pragma unroll
    for (int o = 1; o < 128; o <<= 1) {
        int t = (tid >= o) ? tmp[tid - o] : 0;
        __syncthreads();
        tmp[tid] += t;
        __syncthreads();
    }
    if (tid < nb) g_boff[tid] = tmp[tid] - v;  // exclusive block offsets
}

__global__ void k_scan3(int n, int E) {
    int i = blockIdx.x * blockDim.x + threadIdx.x;
    if (i < n) {
        int r = g_rs[i] + g_boff[i >> 10];
        g_rs[i] = r;
        g_cur[i] = r;
    }
    if (i == 0) g_rs[n] = E;
}

__global__ void k_scatter(int E) {
    int i = blockIdx.x * blockDim.x + threadIdx.x;
    if (i >= E) return;
    int d = g_dst[i];
    int pos = atomicAdd(&g_cur[d], 1);
    g_ssrc[pos] = g_src[i];
}

// ---------------- node transforms --------------------------------------------

// h0 = relu(x @ W0) : [n,128]@[128,16]. Shared-staged, float4 global loads.
__global__ void __launch_bounds__(256)
k_lin0(const float* __restrict__ x, const float* __restrict__ W0, int n) {
    __shared__ float sx[16 * 128];   // 16 rows of x
    __shared__ float sw[128 * 16];   // W0
    int tid = threadIdx.x;
    int row0 = blockIdx.x * 16;
    for (int i = tid; i < 512; i += 256)
        ((float4*)sw)[i] = ((const float4*)W0)[i];
    for (int i = tid; i < 512; i += 256) {
        int r = i >> 5;                // row within tile
        int row = row0 + r;
        float4 v = make_float4(0.f, 0.f, 0.f, 0.f);
        if (row < n) v = ((const float4*)x)[row * 32 + (i & 31)];
        ((float4*)sx)[i] = v;
    }
    __syncthreads();
    int r = tid >> 4, c = tid & 15;
    const float4* sxr = (const float4*)(sx + r * 128);
    float acc = 0.f;
#pragma unroll
    for (int k4 = 0; k4 < 32; k4++) {
        float4 h = sxr[k4];
        acc = fmaf(h.x, sw[(4 * k4 + 0) * 16 + c], acc);
        acc = fmaf(h.y, sw[(4 * k4 + 1) * 16 + c], acc);
        acc = fmaf(h.z, sw[(4 * k4 + 2) * 16 + c], acc);
        acc = fmaf(h.w, sw[(4 * k4 + 3) * 16 + c], acc);
    }
    int row = row0 + r;
    if (row < n) g_h0[row * 16 + c] = fmaxf(acc, 0.f);
}

// layer-1 transforms: weights in registers (one output column per thread),
// h rows staged in shared (broadcast reads). 64 rows per block.
__global__ void __launch_bounds__(384)
k_node1(const float* __restrict__ Wl, const float* __restrict__ bl,
        const float* __restrict__ Wr, const float* __restrict__ br,
        const float* __restrict__ Wf, const float* __restrict__ bf,
        const float* __restrict__ b1, int n) {
    __shared__ float sh[64 * 16];
    int c = threadIdx.x, ty = threadIdx.y;
    int tid = ty * 96 + c;
    int row0 = blockIdx.x * 64;
    float wl[16], wr[16], wf[16];
#pragma unroll
    for (int k = 0; k < 16; k++) {
        wl[k] = Wl[k * 96 + c];
        wr[k] = Wr[k * 96 + c];
        wf[k] = Wf[k * 96 + c];
    }
    float cbl = bl[c], cbr = br[c], cbf = bf[c] + b1[c];
    for (int i = tid; i < 1024; i += 384) {
        int r = i >> 4, k = i & 15;
        int row = row0 + r;
        sh[i] = (row < n) ? g_h0[row * 16 + k] : 0.f;
    }
    __syncthreads();
    for (int r = ty; r < 64; r += 4) {
        int row = row0 + r;
        if (row >= n) continue;
        float a0 = cbl, a1 = cbr, a2 = cbf;
#pragma unroll
        for (int k = 0; k < 16; k++) {
            float h = sh[r * 16 + k];
            a0 = fmaf(h, wl[k], a0);
            a1 = fmaf(h, wr[k], a1);
            a2 = fmaf(h, wf[k], a2);
        }
        g_hl[row * 96 + c] = a0;
        g_hr[row * 96 + c] = a1;
        g_acc[row * 96 + c] = a2;
    }
}

// layer-2 transforms, restructured after R12 probe (occ 18.8%, 12 syncs,
// 316us full-scale): 64 rows/block, whole-K shared tile loaded ONCE (one
// sync), single k=0..95 loop where each broadcast LDS.64 row-pair feeds 3
// FFMA2 (l/r/o matrices together). launch_bounds(384,2) -> 2 blocks/SM.
// Shared tile [k][row] stride 66: LDS.64 aligned, warp-uniform (broadcast).
// probe!=0: ALL writes go to g_probe scratch (ncu measurement launch).
__global__ void __launch_bounds__(384, 2)
k_node2(const float* __restrict__ Wl, const float* __restrict__ bl,
        const float* __restrict__ Wr, const float* __restrict__ br,
        const float* __restrict__ Wo, const float* __restrict__ bo,
        const float* __restrict__ b2, float* __restrict__ out, int probe, int n) {
    __shared__ float sh[96 * 66];
    int c = threadIdx.x, ty = threadIdx.y;
    int tid = ty * 96 + c;
    int row0 = blockIdx.x * 64;
    float* ohl = probe ? g_probe : g_hl;
    float* ohr = probe ? g_probe : g_hr;
    float* oo  = probe ? g_probe : out;

    // load whole 64x96 tile, relu'd, transposed [k][row]
    for (int i = tid; i < 6144; i += 384) {
        int row = i / 96;
        int k = i - row * 96;
        int grow = row0 + row;
        float v = (grow < n) ? g_acc[grow * 96 + k] : 0.f;
        sh[k * 66 + row] = fmaxf(v, 0.f);
    }

    ull a0[8], a1[8], a2[8];
    float ibl = bl[c], ibr = br[c], ibo = bo[c] + b2[c];
#pragma unroll
    for (int jp = 0; jp < 8; jp++) {
        a0[jp] = pack2(ibl, ibl);
        a1[jp] = pack2(ibr, ibr);
        a2[jp] = pack2(ibo, ibo);
    }
    __syncthreads();

#pragma unroll 2
    for (int k = 0; k < 96; k++) {
        float wl = Wl[k * 96 + c];       // coalesced (c consecutive in warp)
        float wr = Wr[k * 96 + c];
        float wo = Wo[k * 96 + c];
        ull wl2 = pack2(wl, wl);
        ull wr2 = pack2(wr, wr);
        ull wo2 = pack2(wo, wo);
        const float* shk = sh + k * 66;
#pragma unroll
        for (int jp = 0; jp < 8; jp++) {
            int p = ty + 4 * jp;         // row-pair index 0..31
            ull h2 = *(const ull*)&shk[2 * p];
            ffma2(a0[jp], h2, wl2);
            ffma2(a1[jp], h2, wr2);
            ffma2(a2[jp], h2, wo2);
        }
    }

#pragma unroll
    for (int jp = 0; jp < 8; jp++) {
        int p = ty + 4 * jp;
        float2 v0 = unpack2(a0[jp]);
        float2 v1 = unpack2(a1[jp]);
        float2 v2 = unpack2(a2[jp]);
        int ra = row0 + 2 * p, rb = ra + 1;
        if (ra < n) {
            ohl[ra * 96 + c] = v0.x; ohr[ra * 96 + c] = v1.x; oo[ra * 96 + c] = v2.x;
        }
        if (rb < n) {
            ohl[rb * 96 + c] = v0.y; ohr[rb * 96 + c] = v1.y; oo[rb * 96 + c] = v2.y;
        }
    }
}

// ---------------- fused GATv2 edge phase: warp per node, 4 edges x 8 lanes ---
// Lane = 8*grp + g. Group grp handles edge (base+grp); lane owns channels
// {4g..4g+3} of each head (float4). One SHFL reduces all 4 edges at once.
// mode: 0 = write ext_out, 1 = write g_acc.
// launch_bounds(256,4): 4 blocks/SM (32 warps) — R11 probe showed latency-bound.
// NOTE: internal target (g_acc) resolved in DEVICE code (host symbol != dev ptr).
__global__ void __launch_bounds__(256, 4)
k_gat(const float* __restrict__ att, float* __restrict__ ext_out,
      int mode, int n) {
    int v = (blockIdx.x * blockDim.x + threadIdx.x) >> 5;
    int lane = threadIdx.x & 31;
    if (v >= n) return;
    float* out = (mode == 1) ? g_acc : ext_out;
    int grp = lane >> 3, g = lane & 7;
    int beg = g_rs[v], end = g_rs[v + 1];
    const float L2E = 1.44269504088896340736f;

    const float4* attv = (const float4*)att;
    float4 at0 = attv[g], at1 = attv[8 + g], at2 = attv[16 + g];
    at0.x *= L2E; at0.y *= L2E; at0.z *= L2E; at0.w *= L2E;
    at1.x *= L2E; at1.y *= L2E; at1.z *= L2E; at1.w *= L2E;
    at2.x *= L2E; at2.y *= L2E; at2.z *= L2E; at2.w *= L2E;

    const float4* hrv = (const float4*)(g_hr + (size_t)v * 96);
    float4 hr0 = hrv[g], hr1 = hrv[8 + g], hr2 = hrv[16 + g];

    float4 ac0 = make_float4(0.f, 0.f, 0.f, 0.f);
    float4 ac1 = ac0, ac2 = ac0;
    float den0 = 0.f, den1 = 0.f, den2 = 0.f;

#pragma unroll 2
    for (int base = beg; base < end; base += 4) {
        int e = base + grp;
        bool valid = (e < end);
        int ee = valid ? e : end - 1;
        int s = g_ssrc[ee];
        const float4* hlv = (const float4*)(g_hl + (size_t)s * 96);
        float4 h0 = hlv[g], h1 = hlv[8 + g], h2 = hlv[16 + g];

        float s0, s1, s2, t;
        t = h0.x + hr0.x; t = fmaxf(t, NEG * t); s0 = at0.x * t;
        t = h0.y + hr0.y; t = fmaxf(t, NEG * t); s0 = fmaf(at0.y, t, s0);
        t = h0.z + hr0.z; t = fmaxf(t, NEG * t); s0 = fmaf(at0.z, t, s0);
        t = h0.w + hr0.w; t = fmaxf(t, NEG * t); s0 = fmaf(at0.w, t, s0);
        t = h1.x + hr1.x; t = fmaxf(t, NEG * t); s1 = at1.x * t;
        t = h1.y + hr1.y; t = fmaxf(t, NEG * t); s1 = fmaf(at1.y, t, s1);
        t = h1.z + hr1.z; t = fmaxf(t, NEG * t); s1 = fmaf(at1.z, t, s1);
        t = h1.w + hr1.w; t = fmaxf(t, NEG * t); s1 = fmaf(at1.w, t, s1);
        t = h2.x + hr2.x; t = fmaxf(t, NEG * t); s2 = at2.x * t;
        t = h2.y + hr2.y; t = fmaxf(t, NEG * t); s2 = fmaf(at2.y, t, s2);
        t = h2.z + hr2.z; t = fmaxf(t, NEG * t); s2 = fmaf(at2.z, t, s2);
        t = h2.w + hr2.w; t = fmaxf(t, NEG * t); s2 = fmaf(at2.w, t, s2);

#pragma unroll
        for (int o = 4; o; o >>= 1) {           // reduce within 8-lane group
            s0 += __shfl_xor_sync(0xffffffffu, s0, o);
            s1 += __shfl_xor_sync(0xffffffffu, s1, o);
            s2 += __shfl_xor_sync(0xffffffffu, s2, o);
        }
        float p0 = valid ? ex2(s0) : 0.f;
        float p1 = valid ? ex2(s1) : 0.f;
        float p2 = valid ? ex2(s2) : 0.f;
        den0 += p0; den1 += p1; den2 += p2;
        ac0.x = fmaf(p0, h0.x, ac0.x); ac0.y = fmaf(p0, h0.y, ac0.y);
        ac0.z = fmaf(p0, h0.z, ac0.z); ac0.w = fmaf(p0, h0.w, ac0.w);
        ac1.x = fmaf(p1, h1.x, ac1.x); ac1.y = fmaf(p1, h1.y, ac1.y);
        ac1.z = fmaf(p1, h1.z, ac1.z); ac1.w = fmaf(p1, h1.w, ac1.w);
        ac2.x = fmaf(p2, h2.x, ac2.x); ac2.y = fmaf(p2, h2.y, ac2.y);
        ac2.z = fmaf(p2, h2.z, ac2.z); ac2.w = fmaf(p2, h2.w, ac2.w);
    }

    // cross-group combine (once per node): sum over the 4 groups
#pragma unroll
    for (int o = 8; o <= 16; o <<= 1) {
        den0 += __shfl_xor_sync(0xffffffffu, den0, o);
        den1 += __shfl_xor_sync(0xffffffffu, den1, o);
        den2 += __shfl_xor_sync(0xffffffffu, den2, o);
        ac0.x += __shfl_xor_sync(0xffffffffu, ac0.x, o);
        ac0.y += __shfl_xor_sync(0xffffffffu, ac0.y, o);
        ac0.z += __shfl_xor_sync(0xffffffffu, ac0.z, o);
        ac0.w += __shfl_xor_sync(0xffffffffu, ac0.w, o);
        ac1.x += __shfl_xor_sync(0xffffffffu, ac1.x, o);
        ac1.y += __shfl_xor_sync(0xffffffffu, ac1.y, o);
        ac1.z += __shfl_xor_sync(0xffffffffu, ac1.z, o);
        ac1.w += __shfl_xor_sync(0xffffffffu, ac1.w, o);
        ac2.x += __shfl_xor_sync(0xffffffffu, ac2.x, o);
        ac2.y += __shfl_xor_sync(0xffffffffu, ac2.y, o);
        ac2.z += __shfl_xor_sync(0xffffffffu, ac2.z, o);
        ac2.w += __shfl_xor_sync(0xffffffffu, ac2.w, o);
    }

    if (grp == 0) {
        float r0 = __fdividef(1.f, den0 + 1e-16f);
        float r1 = __fdividef(1.f, den1 + 1e-16f);
        float r2 = __fdividef(1.f, den2 + 1e-16f);
        float4* orow = (float4*)(out + (size_t)v * 96);
        float4 o0 = orow[g], o1 = orow[8 + g], o2 = orow[16 + g];
        o0.x = fmaf(ac0.x, r0, o0.x); o0.y = fmaf(ac0.y, r0, o0.y);
        o0.z = fmaf(ac0.z, r0, o0.z); o0.w = fmaf(ac0.w, r0, o0.w);
        o1.x = fmaf(ac1.x, r1, o1.x); o1.y = fmaf(ac1.y, r1, o1.y);
        o1.z = fmaf(ac1.z, r1, o1.z); o1.w = fmaf(ac1.w, r1, o1.w);
        o2.x = fmaf(ac2.x, r2, o2.x); o2.y = fmaf(ac2.y, r2, o2.y);
        o2.z = fmaf(ac2.z, r2, o2.z); o2.w = fmaf(ac2.w, r2, o2.w);
        orow[g] = o0; orow[8 + g] = o1; orow[16 + g] = o2;
    }
}

// ---------------- launch ------------------------------------------------------

extern "C" void kernel_launch(void* const* d_in, const int* in_sizes, int n_in,
                              void* d_out, int out_size) {
    const float* x     = (const float*)d_in[0];
    const void*  ei    = (const void*)d_in[1];
    const float* W0    = (const float*)d_in[2];
    const float* Wl1   = (const float*)d_in[3];
    const float* bl1   = (const float*)d_in[4];
    const float* Wr1   = (const float*)d_in[5];
    const float* br1   = (const float*)d_in[6];
    const float* att1  = (const float*)d_in[7];
    const float* b1    = (const float*)d_in[8];
    const float* Wf    = (const float*)d_in[9];
    const float* bf    = (const float*)d_in[10];
    const float* Wl2   = (const float*)d_in[11];
    const float* bl2   = (const float*)d_in[12];
    const float* Wr2   = (const float*)d_in[13];
    const float* br2   = (const float*)d_in[14];
    const float* att2  = (const float*)d_in[15];
    const float* b2    = (const float*)d_in[16];
    const float* Wlast = (const float*)d_in[17];
    const float* blast = (const float*)d_in[18];
    float* out = (float*)d_out;

    int n = in_sizes[0] / 128;
    int E = in_sizes[1] / 2;
    int NB = (n + 1023) / 1024;          // scan blocks (<=128)
    int nprobe = n / 8;

    // ncu captures launch idx 3 -> 1/8-scale probe of the NEW k_node2.
    // Probe reads g_acc (deterministic across replays) and writes ONLY the
    // g_probe scratch, so correctness output is unaffected.
    k_init<<<(n + 255) / 256, 256>>>((const int*)ei, n);
    k_edges<<<(E + 255) / 256, 256>>>(ei, E);
    k_lin0<<<(n + 15) / 16, 256>>>(x, W0, n);
    k_node2<<<(nprobe + 63) / 64, dim3(96, 4)>>>(Wl2, bl2, Wr2, br2, Wlast, blast,
                                                 b2, out, 1, nprobe);  // PROBE (idx 3)
    k_node1<<<(n + 63) / 64, dim3(96, 4)>>>(Wl1, bl1, Wr1, br1, Wf, bf, b1, n);
    k_scan1<<<NB, 1024>>>(n);
    k_scan2<<<1, 128>>>(NB);
    k_scan3<<<(n + 255) / 256, 256>>>(n, E);
    k_scatter<<<(E + 255) / 256, 256>>>(E);

    // ---- layer 1 edge phase (into g_acc which holds skip + b1) ----
    k_gat<<<(n + 7) / 8, 256>>>(att1, out, 1, n);

    // ---- layer 2 node transforms (relu fused on load; out gets skip + b2) ----
    k_node2<<<(n + 63) / 64, dim3(96, 4)>>>(Wl2, bl2, Wr2, br2, Wlast, blast,
                                            b2, out, 0, n);

    // ---- layer 2 edge phase (into d_out) ----
    k_gat<<<(n + 7) / 8, 256>>>(att2, out, 0, n);
}

// round 14
// speedup vs baseline: 1.2285x; 1.0158x over previous
#include <cuda_runtime.h>

#define MAXN 100000
#define MAXE 1600000
#define NEG 0.2f

typedef unsigned long long ull;

// ---------------- scratch (static device globals; no allocation) -------------
__device__ float g_h0 [MAXN * 16];    // relu(x@W0)
__device__ float g_hl [MAXN * 96];    // source transform (current layer)
__device__ float g_hr [MAXN * 96];    // target transform (current layer)
__device__ float g_acc[MAXN * 96];    // layer-1 accumulator = skip + b1 + msgs
__device__ float g_probe[MAXN * 96];  // dead scratch for the ncu probe launch
__device__ int   g_src[MAXE];
__device__ int   g_dst[MAXE];
__device__ int   g_ssrc[MAXE];        // src ids sorted by dst (CSR payload)
__device__ int   g_cnt[MAXN];         // in-degree histogram
__device__ int   g_rs [MAXN + 1];     // CSR row starts
__device__ int   g_cur[MAXN];         // scatter cursors
__device__ int   g_bsum[128];
__device__ int   g_boff[128];
__device__ int   g_is64;

// ---------------- asm helpers -------------------------------------------------
__device__ __forceinline__ void ffma2(ull& acc, ull a, ull b) {
    asm("fma.rn.f32x2 %0, %1, %2, %0;" : "+l"(acc) : "l"(a), "l"(b));
}
__device__ __forceinline__ ull pack2(float x, float y) {
    ull r; asm("mov.b64 %0, {%1, %2};" : "=l"(r) : "f"(x), "f"(y)); return r;
}
__device__ __forceinline__ float2 unpack2(ull v) {
    float2 r; asm("mov.b64 {%0, %1}, %2;" : "=f"(r.x), "=f"(r.y) : "l"(v)); return r;
}
__device__ __forceinline__ float ex2(float v) {
    float r; asm("ex2.approx.ftz.f32 %0, %1;" : "=f"(r) : "f"(v)); return r;
}

// ---------------- init: zero histogram + dtype detect -------------------------
// Detect int64 vs int32 edge_index: node ids < 2^17, so int64 => odd words 0.
__global__ void k_init(const int* __restrict__ p, int n) {
    int i = blockIdx.x * blockDim.x + threadIdx.x;
    if (i < n) g_cnt[i] = 0;
    if (i == 0) {
        int acc = 0;
#pragma unroll
        for (int j = 1; j < 64; j += 2) acc |= p[j];
        g_is64 = (acc == 0) ? 1 : 0;
    }
}

__global__ void k_edges(const void* __restrict__ ei, int E) {
    int i = blockIdx.x * blockDim.x + threadIdx.x;
    if (i >= E) return;
    int s, d;
    if (g_is64) {
        const long long* p = (const long long*)ei;
        s = (int)p[i]; d = (int)p[E + i];
    } else {
        const int* p = (const int*)ei;
        s = p[i]; d = p[E + i];
    }
    g_src[i] = s;
    g_dst[i] = d;
    atomicAdd(&g_cnt[d], 1);
}

// ---------------- scan (3-kernel exclusive prefix sum over g_cnt) ------------

__global__ void k_scan1(int n) {
    __shared__ int tmp[1024];
    int tid = threadIdx.x;
    int i = blockIdx.x * 1024 + tid;
    int v = (i < n) ? g_cnt[i] : 0;
    tmp[tid] = v;
    __syncthreads();
#pragma unroll
    for (int o = 1; o < 1024; o <<= 1) {
        int t = (tid >= o) ? tmp[tid - o] : 0;
        __syncthreads();
        tmp[tid] += t;
        __syncthreads();
    }
    if (i < n) g_rs[i] = tmp[tid] - v;         // block-local exclusive
    if (tid == 1023) g_bsum[blockIdx.x] = tmp[tid];
}

__global__ void k_scan2(int nb) {
    __shared__ int tmp[128];
    int tid = threadIdx.x;
    int v = (tid < nb) ? g_bsum[tid] : 0;
    tmp[tid] = v;
    __syncthreads();
#pragma unroll
    for (int o = 1; o < 128; o <<= 1) {
        int t = (tid >= o) ? tmp[tid - o] : 0;
        __syncthreads();
        tmp[tid] += t;
        __syncthreads();
    }
    if (tid < nb) g_boff[tid] = tmp[tid] - v;  // exclusive block offsets
}

__global__ void k_scan3(int n, int E) {
    int i = blockIdx.x * blockDim.x + threadIdx.x;
    if (i < n) {
        int r = g_rs[i] + g_boff[i >> 10];
        g_rs[i] = r;
        g_cur[i] = r;
    }
    if (i == 0) g_rs[n] = E;
}

__global__ void k_scatter(int E) {
    int i = blockIdx.x * blockDim.x + threadIdx.x;
    if (i >= E) return;
    int d = g_dst[i];
    int pos = atomicAdd(&g_cur[d], 1);
    g_ssrc[pos] = g_src[i];
}

// ---------------- node transforms --------------------------------------------

// h0 = relu(x @ W0) : [n,128]@[128,16]. Shared-staged, float4 global loads.
__global__ void __launch_bounds__(256)
k_lin0(const float* __restrict__ x, const float* __restrict__ W0, int n) {
    __shared__ float sx[16 * 128];   // 16 rows of x
    __shared__ float sw[128 * 16];   // W0
    int tid = threadIdx.x;
    int row0 = blockIdx.x * 16;
    for (int i = tid; i < 512; i += 256)
        ((float4*)sw)[i] = ((const float4*)W0)[i];
    for (int i = tid; i < 512; i += 256) {
        int r = i >> 5;                // row within tile
        int row = row0 + r;
        float4 v = make_float4(0.f, 0.f, 0.f, 0.f);
        if (row < n) v = ((const float4*)x)[row * 32 + (i & 31)];
        ((float4*)sx)[i] = v;
    }
    __syncthreads();
    int r = tid >> 4, c = tid & 15;
    const float4* sxr = (const float4*)(sx + r * 128);
    float acc = 0.f;
#pragma unroll
    for (int k4 = 0; k4 < 32; k4++) {
        float4 h = sxr[k4];
        acc = fmaf(h.x, sw[(4 * k4 + 0) * 16 + c], acc);
        acc = fmaf(h.y, sw[(4 * k4 + 1) * 16 + c], acc);
        acc = fmaf(h.z, sw[(4 * k4 + 2) * 16 + c], acc);
        acc = fmaf(h.w, sw[(4 * k4 + 3) * 16 + c], acc);
    }
    int row = row0 + r;
    if (row < n) g_h0[row * 16 + c] = fmaxf(acc, 0.f);
}

// layer-1 transforms: weights in registers (one output column per thread),
// h rows staged in shared (broadcast reads). 64 rows per block.
__global__ void __launch_bounds__(384)
k_node1(const float* __restrict__ Wl, const float* __restrict__ bl,
        const float* __restrict__ Wr, const float* __restrict__ br,
        const float* __restrict__ Wf, const float* __restrict__ bf,
        const float* __restrict__ b1, int n) {
    __shared__ float sh[64 * 16];
    int c = threadIdx.x, ty = threadIdx.y;
    int tid = ty * 96 + c;
    int row0 = blockIdx.x * 64;
    float wl[16], wr[16], wf[16];
#pragma unroll
    for (int k = 0; k < 16; k++) {
        wl[k] = Wl[k * 96 + c];
        wr[k] = Wr[k * 96 + c];
        wf[k] = Wf[k * 96 + c];
    }
    float cbl = bl[c], cbr = br[c], cbf = bf[c] + b1[c];
    for (int i = tid; i < 1024; i += 384) {
        int r = i >> 4, k = i & 15;
        int row = row0 + r;
        sh[i] = (row < n) ? g_h0[row * 16 + k] : 0.f;
    }
    __syncthreads();
    for (int r = ty; r < 64; r += 4) {
        int row = row0 + r;
        if (row >= n) continue;
        float a0 = cbl, a1 = cbr, a2 = cbf;
#pragma unroll
        for (int k = 0; k < 16; k++) {
            float h = sh[r * 16 + k];
            a0 = fmaf(h, wl[k], a0);
            a1 = fmaf(h, wr[k], a1);
            a2 = fmaf(h, wf[k], a2);
        }
        g_hl[row * 96 + c] = a0;
        g_hr[row * 96 + c] = a1;
        g_acc[row * 96 + c] = a2;
    }
}

// layer-2 transforms. R13 probe: fma 25%, issue 27% — the 3 LDG/k (weights)
// in the inner loop serialize the FFMA2 chains. Fix: K chunked 6x16, each
// chunk's weights staged to SHARED (one coalesced float4/thread/matrix),
// inner loop is pure LDS (<=29cyc) + FFMA2 -> FFMA2-pipe-bound (~82us floor).
// Tile [k][row] stride 68 (16B-aligned rows): thread owns row-QUADS so each
// LDS.128 feeds 6 FFMA2. probe!=0: writes go to g_probe scratch.
__global__ void __launch_bounds__(384, 2)
k_node2(const float* __restrict__ Wl, const float* __restrict__ bl,
        const float* __restrict__ Wr, const float* __restrict__ br,
        const float* __restrict__ Wo, const float* __restrict__ bo,
        const float* __restrict__ b2, float* __restrict__ out, int probe, int n) {
    __shared__ float sh[96 * 68];          // 26112 B
    __shared__ float sw[3 * 16 * 96];      // 18432 B (chunk weights)
    int c = threadIdx.x, ty = threadIdx.y;
    int tid = ty * 96 + c;
    int row0 = blockIdx.x * 64;
    float* ohl = probe ? g_probe : g_hl;
    float* ohr = probe ? g_probe : g_hr;
    float* oo  = probe ? g_probe : out;

    // load whole 64x96 tile, relu'd, transposed [k][row]
    for (int i = tid; i < 6144; i += 384) {
        int row = i / 96;
        int k = i - row * 96;
        int grow = row0 + row;
        float v = (grow < n) ? g_acc[grow * 96 + k] : 0.f;
        sh[k * 68 + row] = fmaxf(v, 0.f);
    }

    // accumulators: 4 row-quads (q = ty + 4*jq), 2 ulls per quad per matrix
    ull a0[4][2], a1[4][2], a2[4][2];
    float ibl = bl[c], ibr = br[c], ibo = bo[c] + b2[c];
#pragma unroll
    for (int jq = 0; jq < 4; jq++) {
        a0[jq][0] = a0[jq][1] = pack2(ibl, ibl);
        a1[jq][0] = a1[jq][1] = pack2(ibr, ibr);
        a2[jq][0] = a2[jq][1] = pack2(ibo, ibo);
    }

    for (int ch = 0; ch < 6; ch++) {
        __syncthreads();                   // tile ready (ch=0) / prev chunk done
        {   // stage chunk weights: 16 k-rows x 96 c = 1536 floats per matrix
            const float4* pl = (const float4*)(Wl + ch * 1536);
            const float4* pr = (const float4*)(Wr + ch * 1536);
            const float4* po = (const float4*)(Wo + ch * 1536);
            ((float4*)sw)[tid]          = pl[tid];
            ((float4*)(sw + 1536))[tid] = pr[tid];
            ((float4*)(sw + 3072))[tid] = po[tid];
        }
        __syncthreads();
#pragma unroll 4
        for (int kk = 0; kk < 16; kk++) {
            float wl = sw[kk * 96 + c];            // lane-distinct, conflict-free
            float wr = sw[1536 + kk * 96 + c];
            float wo = sw[3072 + kk * 96 + c];
            ull wl2 = pack2(wl, wl);
            ull wr2 = pack2(wr, wr);
            ull wo2 = pack2(wo, wo);
            const float* shk = sh + (ch * 16 + kk) * 68;
#pragma unroll
            for (int jq = 0; jq < 4; jq++) {
                int q = ty + 4 * jq;
                longlong2 h = *(const longlong2*)&shk[4 * q];  // rows 4q..4q+3
                ull ha = (ull)h.x, hb = (ull)h.y;
                ffma2(a0[jq][0], ha, wl2); ffma2(a0[jq][1], hb, wl2);
                ffma2(a1[jq][0], ha, wr2); ffma2(a1[jq][1], hb, wr2);
                ffma2(a2[jq][0], ha, wo2); ffma2(a2[jq][1], hb, wo2);
            }
        }
    }

#pragma unroll
    for (int jq = 0; jq < 4; jq++) {
        int q = ty + 4 * jq;
#pragma unroll
        for (int half = 0; half < 2; half++) {
            float2 v0 = unpack2(a0[jq][half]);
            float2 v1 = unpack2(a1[jq][half]);
            float2 v2 = unpack2(a2[jq][half]);
            int ra = row0 + 4 * q + 2 * half, rb = ra + 1;
            if (ra < n) {
                ohl[ra * 96 + c] = v0.x; ohr[ra * 96 + c] = v1.x; oo[ra * 96 + c] = v2.x;
            }
            if (rb < n) {
                ohl[rb * 96 + c] = v0.y; ohr[rb * 96 + c] = v1.y; oo[rb * 96 + c] = v2.y;
            }
        }
    }
}

// ---------------- fused GATv2 edge phase: warp per node, 4 edges x 8 lanes ---
// Lane = 8*grp + g. Group grp handles edge (base+grp); lane owns channels
// {4g..4g+3} of each head (float4). One SHFL reduces all 4 edges at once.
// mode: 0 = write ext_out, 1 = write g_acc.
// launch_bounds(256,4): 4 blocks/SM (32 warps) — R11 probe showed latency-bound.
// NOTE: internal target (g_acc) resolved in DEVICE code (host symbol != dev ptr).
__global__ void __launch_bounds__(256, 4)
k_gat(const float* __restrict__ att, float* __restrict__ ext_out,
      int mode, int n) {
    int v = (blockIdx.x * blockDim.x + threadIdx.x) >> 5;
    int lane = threadIdx.x & 31;
    if (v >= n) return;
    float* out = (mode == 1) ? g_acc : ext_out;
    int grp = lane >> 3, g = lane & 7;
    int beg = g_rs[v], end = g_rs[v + 1];
    const float L2E = 1.44269504088896340736f;

    const float4* attv = (const float4*)att;
    float4 at0 = attv[g], at1 = attv[8 + g], at2 = attv[16 + g];
    at0.x *= L2E; at0.y *= L2E; at0.z *= L2E; at0.w *= L2E;
    at1.x *= L2E; at1.y *= L2E; at1.z *= L2E; at1.w *= L2E;
    at2.x *= L2E; at2.y *= L2E; at2.z *= L2E; at2.w *= L2E;

    const float4* hrv = (const float4*)(g_hr + (size_t)v * 96);
    float4 hr0 = hrv[g], hr1 = hrv[8 + g], hr2 = hrv[16 + g];

    float4 ac0 = make_float4(0.f, 0.f, 0.f, 0.f);
    float4 ac1 = ac0, ac2 = ac0;
    float den0 = 0.f, den1 = 0.f, den2 = 0.f;

#pragma unroll 2
    for (int base = beg; base < end; base += 4) {
        int e = base + grp;
        bool valid = (e < end);
        int ee = valid ? e : end - 1;
        int s = g_ssrc[ee];
        const float4* hlv = (const float4*)(g_hl + (size_t)s * 96);
        float4 h0 = hlv[g], h1 = hlv[8 + g], h2 = hlv[16 + g];

        float s0, s1, s2, t;
        t = h0.x + hr0.x; t = fmaxf(t, NEG * t); s0 = at0.x * t;
        t = h0.y + hr0.y; t = fmaxf(t, NEG * t); s0 = fmaf(at0.y, t, s0);
        t = h0.z + hr0.z; t = fmaxf(t, NEG * t); s0 = fmaf(at0.z, t, s0);
        t = h0.w + hr0.w; t = fmaxf(t, NEG * t); s0 = fmaf(at0.w, t, s0);
        t = h1.x + hr1.x; t = fmaxf(t, NEG * t); s1 = at1.x * t;
        t = h1.y + hr1.y; t = fmaxf(t, NEG * t); s1 = fmaf(at1.y, t, s1);
        t = h1.z + hr1.z; t = fmaxf(t, NEG * t); s1 = fmaf(at1.z, t, s1);
        t = h1.w + hr1.w; t = fmaxf(t, NEG * t); s1 = fmaf(at1.w, t, s1);
        t = h2.x + hr2.x; t = fmaxf(t, NEG * t); s2 = at2.x * t;
        t = h2.y + hr2.y; t = fmaxf(t, NEG * t); s2 = fmaf(at2.y, t, s2);
        t = h2.z + hr2.z; t = fmaxf(t, NEG * t); s2 = fmaf(at2.z, t, s2);
        t = h2.w + hr2.w; t = fmaxf(t, NEG * t); s2 = fmaf(at2.w, t, s2);

#pragma unroll
        for (int o = 4; o; o >>= 1) {           // reduce within 8-lane group
            s0 += __shfl_xor_sync(0xffffffffu, s0, o);
            s1 += __shfl_xor_sync(0xffffffffu, s1, o);
            s2 += __shfl_xor_sync(0xffffffffu, s2, o);
        }
        float p0 = valid ? ex2(s0) : 0.f;
        float p1 = valid ? ex2(s1) : 0.f;
        float p2 = valid ? ex2(s2) : 0.f;
        den0 += p0; den1 += p1; den2 += p2;
        ac0.x = fmaf(p0, h0.x, ac0.x); ac0.y = fmaf(p0, h0.y, ac0.y);
        ac0.z = fmaf(p0, h0.z, ac0.z); ac0.w = fmaf(p0, h0.w, ac0.w);
        ac1.x = fmaf(p1, h1.x, ac1.x); ac1.y = fmaf(p1, h1.y, ac1.y);
        ac1.z = fmaf(p1, h1.z, ac1.z); ac1.w = fmaf(p1, h1.w, ac1.w);
        ac2.x = fmaf(p2, h2.x, ac2.x); ac2.y = fmaf(p2, h2.y, ac2.y);
        ac2.z = fmaf(p2, h2.z, ac2.z); ac2.w = fmaf(p2, h2.w, ac2.w);
    }

    // cross-group combine (once per node): sum over the 4 groups
#pragma unroll
    for (int o = 8; o <= 16; o <<= 1) {
        den0 += __shfl_xor_sync(0xffffffffu, den0, o);
        den1 += __shfl_xor_sync(0xffffffffu, den1, o);
        den2 += __shfl_xor_sync(0xffffffffu, den2, o);
        ac0.x += __shfl_xor_sync(0xffffffffu, ac0.x, o);
        ac0.y += __shfl_xor_sync(0xffffffffu, ac0.y, o);
        ac0.z += __shfl_xor_sync(0xffffffffu, ac0.z, o);
        ac0.w += __shfl_xor_sync(0xffffffffu, ac0.w, o);
        ac1.x += __shfl_xor_sync(0xffffffffu, ac1.x, o);
        ac1.y += __shfl_xor_sync(0xffffffffu, ac1.y, o);
        ac1.z += __shfl_xor_sync(0xffffffffu, ac1.z, o);
        ac1.w += __shfl_xor_sync(0xffffffffu, ac1.w, o);
        ac2.x += __shfl_xor_sync(0xffffffffu, ac2.x, o);
        ac2.y += __shfl_xor_sync(0xffffffffu, ac2.y, o);
        ac2.z += __shfl_xor_sync(0xffffffffu, ac2.z, o);
        ac2.w += __shfl_xor_sync(0xffffffffu, ac2.w, o);
    }

    if (grp == 0) {
        float r0 = __fdividef(1.f, den0 + 1e-16f);
        float r1 = __fdividef(1.f, den1 + 1e-16f);
        float r2 = __fdividef(1.f, den2 + 1e-16f);
        float4* orow = (float4*)(out + (size_t)v * 96);
        float4 o0 = orow[g], o1 = orow[8 + g], o2 = orow[16 + g];
        o0.x = fmaf(ac0.x, r0, o0.x); o0.y = fmaf(ac0.y, r0, o0.y);
        o0.z = fmaf(ac0.z, r0, o0.z); o0.w = fmaf(ac0.w, r0, o0.w);
        o1.x = fmaf(ac1.x, r1, o1.x); o1.y = fmaf(ac1.y, r1, o1.y);
        o1.z = fmaf(ac1.z, r1, o1.z); o1.w = fmaf(ac1.w, r1, o1.w);
        o2.x = fmaf(ac2.x, r2, o2.x); o2.y = fmaf(ac2.y, r2, o2.y);
        o2.z = fmaf(ac2.z, r2, o2.z); o2.w = fmaf(ac2.w, r2, o2.w);
        orow[g] = o0; orow[8 + g] = o1; orow[16 + g] = o2;
    }
}

// ---------------- launch ------------------------------------------------------

extern "C" void kernel_launch(void* const* d_in, const int* in_sizes, int n_in,
                              void* d_out, int out_size) {
    const float* x     = (const float*)d_in[0];
    const void*  ei    = (const void*)d_in[1];
    const float* W0    = (const float*)d_in[2];
    const float* Wl1   = (const float*)d_in[3];
    const float* bl1   = (const float*)d_in[4];
    const float* Wr1   = (const float*)d_in[5];
    const float* br1   = (const float*)d_in[6];
    const float* att1  = (const float*)d_in[7];
    const float* b1    = (const float*)d_in[8];
    const float* Wf    = (const float*)d_in[9];
    const float* bf    = (const float*)d_in[10];
    const float* Wl2   = (const float*)d_in[11];
    const float* bl2   = (const float*)d_in[12];
    const float* Wr2   = (const float*)d_in[13];
    const float* br2   = (const float*)d_in[14];
    const float* att2  = (const float*)d_in[15];
    const float* b2    = (const float*)d_in[16];
    const float* Wlast = (const float*)d_in[17];
    const float* blast = (const float*)d_in[18];
    float* out = (float*)d_out;

    int n = in_sizes[0] / 128;
    int E = in_sizes[1] / 2;
    int NB = (n + 1023) / 1024;          // scan blocks (<=128)
    int nprobe = n / 8;

    // ncu captures launch idx 3 -> 1/8-scale probe of the NEW k_node2.
    // Probe reads g_acc (deterministic across replays) and writes ONLY the
    // g_probe scratch, so correctness output is unaffected.
    k_init<<<(n + 255) / 256, 256>>>((const int*)ei, n);
    k_edges<<<(E + 255) / 256, 256>>>(ei, E);
    k_lin0<<<(n + 15) / 16, 256>>>(x, W0, n);
    k_node2<<<(nprobe + 63) / 64, dim3(96, 4)>>>(Wl2, bl2, Wr2, br2, Wlast, blast,
                                                 b2, out, 1, nprobe);  // PROBE (idx 3)
    k_node1<<<(n + 63) / 64, dim3(96, 4)>>>(Wl1, bl1, Wr1, br1, Wf, bf, b1, n);
    k_scan1<<<NB, 1024>>>(n);
    k_scan2<<<1, 128>>>(NB);
    k_scan3<<<(n + 255) / 256, 256>>>(n, E);
    k_scatter<<<(E + 255) / 256, 256>>>(E);

    // ---- layer 1 edge phase (into g_acc which holds skip + b1) ----
    k_gat<<<(n + 7) / 8, 256>>>(att1, out, 1, n);

    // ---- layer 2 node transforms (relu fused on load; out gets skip + b2) ----
    k_node2<<<(n + 63) / 64, dim3(96, 4)>>>(Wl2, bl2, Wr2, br2, Wlast, blast,
                                            b2, out, 0, n);

    // ---- layer 2 edge phase (into d_out) ----
    k_gat<<<(n + 7) / 8, 256>>>(att2, out, 0, n);
}

// round 15
// speedup vs baseline: 1.2801x; 1.0420x over previous
#include <cuda_runtime.h>

#define MAXN 100000
#define MAXE 1600000
#define NEG 0.2f

typedef unsigned long long ull;

// ---------------- scratch (static device globals; no allocation) -------------
__device__ float g_h0 [MAXN * 16];    // relu(x@W0)
__device__ float g_hl [MAXN * 96];    // source transform (current layer)
__device__ float g_hr [MAXN * 96];    // target transform (current layer)
__device__ float g_acc[MAXN * 96];    // layer-1 accumulator = skip + b1 + msgs
__device__ int   g_src[MAXE];
__device__ int   g_dst[MAXE];
__device__ int   g_ssrc[MAXE];        // src ids sorted by dst (CSR payload)
__device__ int   g_cnt[MAXN];         // in-degree histogram
__device__ int   g_rs [MAXN + 1];     // CSR row starts
__device__ int   g_cur[MAXN];         // scatter cursors
__device__ int   g_bsum[128];
__device__ int   g_boff[128];
__device__ int   g_is64;

// ---------------- asm helpers -------------------------------------------------
__device__ __forceinline__ void ffma2(ull& acc, ull a, ull b) {
    asm("fma.rn.f32x2 %0, %1, %2, %0;" : "+l"(acc) : "l"(a), "l"(b));
}
__device__ __forceinline__ ull pack2(float x, float y) {
    ull r; asm("mov.b64 %0, {%1, %2};" : "=l"(r) : "f"(x), "f"(y)); return r;
}
__device__ __forceinline__ float2 unpack2(ull v) {
    float2 r; asm("mov.b64 {%0, %1}, %2;" : "=f"(r.x), "=f"(r.y) : "l"(v)); return r;
}
__device__ __forceinline__ float ex2(float v) {
    float r; asm("ex2.approx.ftz.f32 %0, %1;" : "=f"(r) : "f"(v)); return r;
}

// ---------------- init: zero histogram + dtype detect -------------------------
// Detect int64 vs int32 edge_index: node ids < 2^17, so int64 => odd words 0.
__global__ void k_init(const int* __restrict__ p, int n) {
    int i = blockIdx.x * blockDim.x + threadIdx.x;
    if (i < n) g_cnt[i] = 0;
    if (i == 0) {
        int acc = 0;
#pragma unroll
        for (int j = 1; j < 64; j += 2) acc |= p[j];
        g_is64 = (acc == 0) ? 1 : 0;
    }
}

__global__ void k_edges(const void* __restrict__ ei, int E) {
    int i = blockIdx.x * blockDim.x + threadIdx.x;
    if (i >= E) return;
    int s, d;
    if (g_is64) {
        const long long* p = (const long long*)ei;
        s = (int)p[i]; d = (int)p[E + i];
    } else {
        const int* p = (const int*)ei;
        s = p[i]; d = p[E + i];
    }
    g_src[i] = s;
    g_dst[i] = d;
    atomicAdd(&g_cnt[d], 1);
}

// ---------------- scan (3-kernel exclusive prefix sum over g_cnt) ------------

__global__ void k_scan1(int n) {
    __shared__ int tmp[1024];
    int tid = threadIdx.x;
    int i = blockIdx.x * 1024 + tid;
    int v = (i < n) ? g_cnt[i] : 0;
    tmp[tid] = v;
    __syncthreads();
#pragma unroll
    for (int o = 1; o < 1024; o <<= 1) {
        int t = (tid >= o) ? tmp[tid - o] : 0;
        __syncthreads();
        tmp[tid] += t;
        __syncthreads();
    }
    if (i < n) g_rs[i] = tmp[tid] - v;         // block-local exclusive
    if (tid == 1023) g_bsum[blockIdx.x] = tmp[tid];
}

__global__ void k_scan2(int nb) {
    __shared__ int tmp[128];
    int tid = threadIdx.x;
    int v = (tid < nb) ? g_bsum[tid] : 0;
    tmp[tid] = v;
    __syncthreads();
#pragma unroll
    for (int o = 1; o < 128; o <<= 1) {
        int t = (tid >= o) ? tmp[tid - o] : 0;
        __syncthreads();
        tmp[tid] += t;
        __syncthreads();
    }
    if (tid < nb) g_boff[tid] = tmp[tid] - v;  // exclusive block offsets
}

__global__ void k_scan3(int n, int E) {
    int i = blockIdx.x * blockDim.x + threadIdx.x;
    if (i < n) {
        int r = g_rs[i] + g_boff[i >> 10];
        g_rs[i] = r;
        g_cur[i] = r;
    }
    if (i == 0) g_rs[n] = E;
}

__global__ void k_scatter(int E) {
    int i = blockIdx.x * blockDim.x + threadIdx.x;
    if (i >= E) return;
    int d = g_dst[i];
    int pos = atomicAdd(&g_cur[d], 1);
    g_ssrc[pos] = g_src[i];
}

// ---------------- node transforms --------------------------------------------

// h0 = relu(x @ W0) : [n,128]@[128,16]. Shared-staged, float4 global loads.
__global__ void __launch_bounds__(256)
k_lin0(const float* __restrict__ x, const float* __restrict__ W0, int n) {
    __shared__ float sx[16 * 128];   // 16 rows of x
    __shared__ float sw[128 * 16];   // W0
    int tid = threadIdx.x;
    int row0 = blockIdx.x * 16;
    for (int i = tid; i < 512; i += 256)
        ((float4*)sw)[i] = ((const float4*)W0)[i];
    for (int i = tid; i < 512; i += 256) {
        int r = i >> 5;                // row within tile
        int row = row0 + r;
        float4 v = make_float4(0.f, 0.f, 0.f, 0.f);
        if (row < n) v = ((const float4*)x)[row * 32 + (i & 31)];
        ((float4*)sx)[i] = v;
    }
    __syncthreads();
    int r = tid >> 4, c = tid & 15;
    const float4* sxr = (const float4*)(sx + r * 128);
    float acc = 0.f;
#pragma unroll
    for (int k4 = 0; k4 < 32; k4++) {
        float4 h = sxr[k4];
        acc = fmaf(h.x, sw[(4 * k4 + 0) * 16 + c], acc);
        acc = fmaf(h.y, sw[(4 * k4 + 1) * 16 + c], acc);
        acc = fmaf(h.z, sw[(4 * k4 + 2) * 16 + c], acc);
        acc = fmaf(h.w, sw[(4 * k4 + 3) * 16 + c], acc);
    }
    int row = row0 + r;
    if (row < n) g_h0[row * 16 + c] = fmaxf(acc, 0.f);
}

// layer-1 transforms: weights in registers (one output column per thread),
// h rows staged in shared (broadcast reads). 64 rows per block.
__global__ void __launch_bounds__(384)
k_node1(const float* __restrict__ Wl, const float* __restrict__ bl,
        const float* __restrict__ Wr, const float* __restrict__ br,
        const float* __restrict__ Wf, const float* __restrict__ bf,
        const float* __restrict__ b1, int n) {
    __shared__ float sh[64 * 16];
    int c = threadIdx.x, ty = threadIdx.y;
    int tid = ty * 96 + c;
    int row0 = blockIdx.x * 64;
    float wl[16], wr[16], wf[16];
#pragma unroll
    for (int k = 0; k < 16; k++) {
        wl[k] = Wl[k * 96 + c];
        wr[k] = Wr[k * 96 + c];
        wf[k] = Wf[k * 96 + c];
    }
    float cbl = bl[c], cbr = br[c], cbf = bf[c] + b1[c];
    for (int i = tid; i < 1024; i += 384) {
        int r = i >> 4, k = i & 15;
        int row = row0 + r;
        sh[i] = (row < n) ? g_h0[row * 16 + k] : 0.f;
    }
    __syncthreads();
    for (int r = ty; r < 64; r += 4) {
        int row = row0 + r;
        if (row >= n) continue;
        float a0 = cbl, a1 = cbr, a2 = cbf;
#pragma unroll
        for (int k = 0; k < 16; k++) {
            float h = sh[r * 16 + k];
            a0 = fmaf(h, wl[k], a0);
            a1 = fmaf(h, wr[k], a1);
            a2 = fmaf(h, wf[k], a2);
        }
        g_hl[row * 96 + c] = a0;
        g_hr[row * 96 + c] = a1;
        g_acc[row * 96 + c] = a2;
    }
}

// layer-2 transforms (R14 structure): whole-K tile in shared, chunk weights
// staged to shared, inner loop pure LDS + FFMA2.
__global__ void __launch_bounds__(384, 2)
k_node2(const float* __restrict__ Wl, const float* __restrict__ bl,
        const float* __restrict__ Wr, const float* __restrict__ br,
        const float* __restrict__ Wo, const float* __restrict__ bo,
        const float* __restrict__ b2, float* __restrict__ out, int n) {
    __shared__ float sh[96 * 68];          // 26112 B
    __shared__ float sw[3 * 16 * 96];      // 18432 B (chunk weights)
    int c = threadIdx.x, ty = threadIdx.y;
    int tid = ty * 96 + c;
    int row0 = blockIdx.x * 64;

    // load whole 64x96 tile, relu'd, transposed [k][row]
    for (int i = tid; i < 6144; i += 384) {
        int row = i / 96;
        int k = i - row * 96;
        int grow = row0 + row;
        float v = (grow < n) ? g_acc[grow * 96 + k] : 0.f;
        sh[k * 68 + row] = fmaxf(v, 0.f);
    }

    // accumulators: 4 row-quads (q = ty + 4*jq), 2 ulls per quad per matrix
    ull a0[4][2], a1[4][2], a2[4][2];
    float ibl = bl[c], ibr = br[c], ibo = bo[c] + b2[c];
#pragma unroll
    for (int jq = 0; jq < 4; jq++) {
        a0[jq][0] = a0[jq][1] = pack2(ibl, ibl);
        a1[jq][0] = a1[jq][1] = pack2(ibr, ibr);
        a2[jq][0] = a2[jq][1] = pack2(ibo, ibo);
    }

    for (int ch = 0; ch < 6; ch++) {
        __syncthreads();                   // tile ready (ch=0) / prev chunk done
        {   // stage chunk weights: 16 k-rows x 96 c = 1536 floats per matrix
            const float4* pl = (const float4*)(Wl + ch * 1536);
            const float4* pr = (const float4*)(Wr + ch * 1536);
            const float4* po = (const float4*)(Wo + ch * 1536);
            ((float4*)sw)[tid]          = pl[tid];
            ((float4*)(sw + 1536))[tid] = pr[tid];
            ((float4*)(sw + 3072))[tid] = po[tid];
        }
        __syncthreads();
#pragma unroll 4
        for (int kk = 0; kk < 16; kk++) {
            float wl = sw[kk * 96 + c];            // lane-distinct, conflict-free
            float wr = sw[1536 + kk * 96 + c];
            float wo = sw[3072 + kk * 96 + c];
            ull wl2 = pack2(wl, wl);
            ull wr2 = pack2(wr, wr);
            ull wo2 = pack2(wo, wo);
            const float* shk = sh + (ch * 16 + kk) * 68;
#pragma unroll
            for (int jq = 0; jq < 4; jq++) {
                int q = ty + 4 * jq;
                longlong2 h = *(const longlong2*)&shk[4 * q];  // rows 4q..4q+3
                ull ha = (ull)h.x, hb = (ull)h.y;
                ffma2(a0[jq][0], ha, wl2); ffma2(a0[jq][1], hb, wl2);
                ffma2(a1[jq][0], ha, wr2); ffma2(a1[jq][1], hb, wr2);
                ffma2(a2[jq][0], ha, wo2); ffma2(a2[jq][1], hb, wo2);
            }
        }
    }

#pragma unroll
    for (int jq = 0; jq < 4; jq++) {
        int q = ty + 4 * jq;
#pragma unroll
        for (int half = 0; half < 2; half++) {
            float2 v0 = unpack2(a0[jq][half]);
            float2 v1 = unpack2(a1[jq][half]);
            float2 v2 = unpack2(a2[jq][half]);
            int ra = row0 + 4 * q + 2 * half, rb = ra + 1;
            if (ra < n) {
                g_hl[ra * 96 + c] = v0.x; g_hr[ra * 96 + c] = v1.x; out[ra * 96 + c] = v2.x;
            }
            if (rb < n) {
                g_hl[rb * 96 + c] = v0.y; g_hr[rb * 96 + c] = v1.y; out[rb * 96 + c] = v2.y;
            }
        }
    }
}

// ---------------- fused GATv2 edge phase: warp per node, 4 edges x 8 lanes ---
// SOFTWARE-PIPELINED: while batch b's shfl/ex2 chain runs, batch b+1's CSR
// index + 3 float4 h-rows are already in flight (the R11/14 profiles showed
// exposed gather latency; the 64-reg cap of (256,4) blocked hoisting, so
// relax to (256,3) and prefetch explicitly).
// mode: 0 = write ext_out, 1 = write g_acc (resolved in device code).
__global__ void __launch_bounds__(256, 3)
k_gat(const float* __restrict__ att, float* __restrict__ ext_out,
      int mode, int n) {
    int v = (blockIdx.x * blockDim.x + threadIdx.x) >> 5;
    int lane = threadIdx.x & 31;
    if (v >= n) return;
    float* out = (mode == 1) ? g_acc : ext_out;
    int grp = lane >> 3, g = lane & 7;
    int beg = g_rs[v], end = g_rs[v + 1];
    const float L2E = 1.44269504088896340736f;

    const float4* attv = (const float4*)att;
    float4 at0 = attv[g], at1 = attv[8 + g], at2 = attv[16 + g];
    at0.x *= L2E; at0.y *= L2E; at0.z *= L2E; at0.w *= L2E;
    at1.x *= L2E; at1.y *= L2E; at1.z *= L2E; at1.w *= L2E;
    at2.x *= L2E; at2.y *= L2E; at2.z *= L2E; at2.w *= L2E;

    const float4* hrv = (const float4*)(g_hr + (size_t)v * 96);
    float4 hr0 = hrv[g], hr1 = hrv[8 + g], hr2 = hrv[16 + g];

    float4 ac0 = make_float4(0.f, 0.f, 0.f, 0.f);
    float4 ac1 = ac0, ac2 = ac0;
    float den0 = 0.f, den1 = 0.f, den2 = 0.f;

    if (beg < end) {
        // prologue: load batch 0
        int e = beg + grp;
        int ee = (e < end) ? e : end - 1;
        int s = g_ssrc[ee];
        const float4* hlv = (const float4*)(g_hl + (size_t)s * 96);
        float4 h0 = hlv[g], h1 = hlv[8 + g], h2 = hlv[16 + g];

        for (int base = beg; base < end; base += 4) {
            float4 c0 = h0, c1 = h1, c2 = h2;
            bool cvalid = (base + grp) < end;
            int nbase = base + 4;
            if (nbase < end) {                 // prefetch batch b+1
                int e2 = nbase + grp;
                int ee2 = (e2 < end) ? e2 : end - 1;
                int s2 = g_ssrc[ee2];
                const float4* p = (const float4*)(g_hl + (size_t)s2 * 96);
                h0 = p[g]; h1 = p[8 + g]; h2 = p[16 + g];
            }

            float s0, s1, s2v, t;
            t = c0.x + hr0.x; t = fmaxf(t, NEG * t); s0 = at0.x * t;
            t = c0.y + hr0.y; t = fmaxf(t, NEG * t); s0 = fmaf(at0.y, t, s0);
            t = c0.z + hr0.z; t = fmaxf(t, NEG * t); s0 = fmaf(at0.z, t, s0);
            t = c0.w + hr0.w; t = fmaxf(t, NEG * t); s0 = fmaf(at0.w, t, s0);
            t = c1.x + hr1.x; t = fmaxf(t, NEG * t); s1 = at1.x * t;
            t = c1.y + hr1.y; t = fmaxf(t, NEG * t); s1 = fmaf(at1.y, t, s1);
            t = c1.z + hr1.z; t = fmaxf(t, NEG * t); s1 = fmaf(at1.z, t, s1);
            t = c1.w + hr1.w; t = fmaxf(t, NEG * t); s1 = fmaf(at1.w, t, s1);
            t = c2.x + hr2.x; t = fmaxf(t, NEG * t); s2v = at2.x * t;
            t = c2.y + hr2.y; t = fmaxf(t, NEG * t); s2v = fmaf(at2.y, t, s2v);
            t = c2.z + hr2.z; t = fmaxf(t, NEG * t); s2v = fmaf(at2.z, t, s2v);
            t = c2.w + hr2.w; t = fmaxf(t, NEG * t); s2v = fmaf(at2.w, t, s2v);

#pragma unroll
            for (int o = 4; o; o >>= 1) {       // reduce within 8-lane group
                s0  += __shfl_xor_sync(0xffffffffu, s0, o);
                s1  += __shfl_xor_sync(0xffffffffu, s1, o);
                s2v += __shfl_xor_sync(0xffffffffu, s2v, o);
            }
            float p0 = cvalid ? ex2(s0) : 0.f;
            float p1 = cvalid ? ex2(s1) : 0.f;
            float p2 = cvalid ? ex2(s2v) : 0.f;
            den0 += p0; den1 += p1; den2 += p2;
            ac0.x = fmaf(p0, c0.x, ac0.x); ac0.y = fmaf(p0, c0.y, ac0.y);
            ac0.z = fmaf(p0, c0.z, ac0.z); ac0.w = fmaf(p0, c0.w, ac0.w);
            ac1.x = fmaf(p1, c1.x, ac1.x); ac1.y = fmaf(p1, c1.y, ac1.y);
            ac1.z = fmaf(p1, c1.z, ac1.z); ac1.w = fmaf(p1, c1.w, ac1.w);
            ac2.x = fmaf(p2, c2.x, ac2.x); ac2.y = fmaf(p2, c2.y, ac2.y);
            ac2.z = fmaf(p2, c2.z, ac2.z); ac2.w = fmaf(p2, c2.w, ac2.w);
        }
    }

    // cross-group combine (once per node): sum over the 4 groups
#pragma unroll
    for (int o = 8; o <= 16; o <<= 1) {
        den0 += __shfl_xor_sync(0xffffffffu, den0, o);
        den1 += __shfl_xor_sync(0xffffffffu, den1, o);
        den2 += __shfl_xor_sync(0xffffffffu, den2, o);
        ac0.x += __shfl_xor_sync(0xffffffffu, ac0.x, o);
        ac0.y += __shfl_xor_sync(0xffffffffu, ac0.y, o);
        ac0.z += __shfl_xor_sync(0xffffffffu, ac0.z, o);
        ac0.w += __shfl_xor_sync(0xffffffffu, ac0.w, o);
        ac1.x += __shfl_xor_sync(0xffffffffu, ac1.x, o);
        ac1.y += __shfl_xor_sync(0xffffffffu, ac1.y, o);
        ac1.z += __shfl_xor_sync(0xffffffffu, ac1.z, o);
        ac1.w += __shfl_xor_sync(0xffffffffu, ac1.w, o);
        ac2.x += __shfl_xor_sync(0xffffffffu, ac2.x, o);
        ac2.y += __shfl_xor_sync(0xffffffffu, ac2.y, o);
        ac2.z += __shfl_xor_sync(0xffffffffu, ac2.z, o);
        ac2.w += __shfl_xor_sync(0xffffffffu, ac2.w, o);
    }

    if (grp == 0) {
        float r0 = __fdividef(1.f, den0 + 1e-16f);
        float r1 = __fdividef(1.f, den1 + 1e-16f);
        float r2 = __fdividef(1.f, den2 + 1e-16f);
        float4* orow = (float4*)(out + (size_t)v * 96);
        float4 o0 = orow[g], o1 = orow[8 + g], o2 = orow[16 + g];
        o0.x = fmaf(ac0.x, r0, o0.x); o0.y = fmaf(ac0.y, r0, o0.y);
        o0.z = fmaf(ac0.z, r0, o0.z); o0.w = fmaf(ac0.w, r0, o0.w);
        o1.x = fmaf(ac1.x, r1, o1.x); o1.y = fmaf(ac1.y, r1, o1.y);
        o1.z = fmaf(ac1.z, r1, o1.z); o1.w = fmaf(ac1.w, r1, o1.w);
        o2.x = fmaf(ac2.x, r2, o2.x); o2.y = fmaf(ac2.y, r2, o2.y);
        o2.z = fmaf(ac2.z, r2, o2.z); o2.w = fmaf(ac2.w, r2, o2.w);
        orow[g] = o0; orow[8 + g] = o1; orow[16 + g] = o2;
    }
}

// ---------------- launch ------------------------------------------------------

extern "C" void kernel_launch(void* const* d_in, const int* in_sizes, int n_in,
                              void* d_out, int out_size) {
    const float* x     = (const float*)d_in[0];
    const void*  ei    = (const void*)d_in[1];
    const float* W0    = (const float*)d_in[2];
    const float* Wl1   = (const float*)d_in[3];
    const float* bl1   = (const float*)d_in[4];
    const float* Wr1   = (const float*)d_in[5];
    const float* br1   = (const float*)d_in[6];
    const float* att1  = (const float*)d_in[7];
    const float* b1    = (const float*)d_in[8];
    const float* Wf    = (const float*)d_in[9];
    const float* bf    = (const float*)d_in[10];
    const float* Wl2   = (const float*)d_in[11];
    const float* bl2   = (const float*)d_in[12];
    const float* Wr2   = (const float*)d_in[13];
    const float* br2   = (const float*)d_in[14];
    const float* att2  = (const float*)d_in[15];
    const float* b2    = (const float*)d_in[16];
    const float* Wlast = (const float*)d_in[17];
    const float* blast = (const float*)d_in[18];
    float* out = (float*)d_out;

    int n = in_sizes[0] / 128;
    int E = in_sizes[1] / 2;
    int NB = (n + 1023) / 1024;          // scan blocks (<=128)

    k_init<<<(n + 255) / 256, 256>>>((const int*)ei, n);
    k_edges<<<(E + 255) / 256, 256>>>(ei, E);
    k_lin0<<<(n + 15) / 16, 256>>>(x, W0, n);
    k_node1<<<(n + 63) / 64, dim3(96, 4)>>>(Wl1, bl1, Wr1, br1, Wf, bf, b1, n);
    k_scan1<<<NB, 1024>>>(n);
    k_scan2<<<1, 128>>>(NB);
    k_scan3<<<(n + 255) / 256, 256>>>(n, E);
    k_scatter<<<(E + 255) / 256, 256>>>(E);

    // ---- layer 1 edge phase (into g_acc which holds skip + b1) ----
    k_gat<<<(n + 7) / 8, 256>>>(att1, out, 1, n);

    // ---- layer 2 node transforms (relu fused on load; out gets skip + b2) ----
    k_node2<<<(n + 63) / 64, dim3(96, 4)>>>(Wl2, bl2, Wr2, br2, Wlast, blast,
                                            b2, out, n);

    // ---- layer 2 edge phase (into d_out) ----
    k_gat<<<(n + 7) / 8, 256>>>(att2, out, 0, n);
}